// round 12
// baseline (speedup 1.0000x reference)
#include <cuda_runtime.h>
#include <cuda_bf16.h>
#include <math.h>
#include <stdint.h>

// ---------------------------------------------------------------------------
// Model dims
// ---------------------------------------------------------------------------
#define DIM   1024
#define FFDIM 4096
#define VOC   32000
#define SEQ   1024
#define BATCH 2
#define MTOK  (BATCH * SEQ)

#define LAYER0_OFF   32768000LL
#define LAYER_STRIDE 16777216LL
#define NWEIGHT      (2 * LAYER_STRIDE + (long long)VOC * DIM)

// ---------------------------------------------------------------------------
// Scratch
// ---------------------------------------------------------------------------
__device__ float g_w   [NWEIGHT];            // tf32-rounded weights
__device__ float g_h   [MTOK * DIM];
__device__ float g_qkv [MTOK * 3 * DIM];     // q,k pair-interleaved; v unused
__device__ float g_vt  [BATCH * DIM * SEQ];
__device__ float g_s   [BATCH * SEQ * SEQ];
__device__ float g_a   [MTOK * DIM];
__device__ float g_t   [MTOK * FFDIM];
__device__ float g_part[4LL * BATCH * SEQ * SEQ]; // split-K partials (4 slices)

// ---------------------------------------------------------------------------
// helpers
// ---------------------------------------------------------------------------
__device__ __forceinline__ uint32_t f2tf32(float x) {
    uint32_t r;
    asm("cvt.rna.tf32.f32 %0, %1;" : "=r"(r) : "f"(x));
    return r;
}
__device__ __forceinline__ float round_tf32(float x) {
    return __uint_as_float(f2tf32(x));
}
__device__ __forceinline__ uint32_t smem_u32(const void* p) {
    uint32_t a;
    asm("{ .reg .u64 t; cvta.to.shared.u64 t, %1; cvt.u32.u64 %0, t; }" : "=r"(a) : "l"(p));
    return a;
}
#define CP_ASYNC16(dst, src) \
    asm volatile("cp.async.cg.shared.global [%0], [%1], 16;" :: "r"(dst), "l"(src))
#define CP_COMMIT() asm volatile("cp.async.commit_group;" ::: "memory")
#define CP_WAIT(n)  asm volatile("cp.async.wait_group %0;" :: "n"(n) : "memory")

__device__ __forceinline__ void mma16n8k8(float c[4], const uint32_t a[4],
                                          const uint32_t b[2]) {
    asm volatile(
        "mma.sync.aligned.m16n8k8.row.col.f32.tf32.tf32.f32 "
        "{%0,%1,%2,%3}, {%4,%5,%6,%7}, {%8,%9}, {%0,%1,%2,%3};"
        : "+f"(c[0]), "+f"(c[1]), "+f"(c[2]), "+f"(c[3])
        : "r"(a[0]), "r"(a[1]), "r"(a[2]), "r"(a[3]), "r"(b[0]), "r"(b[1]));
}

// ---------------------------------------------------------------------------
// tf32 GEMM, cp.async 3-stage, 128 threads, 4 warps (2Mx2N), warp tile 64x64,
// 3 CTAs/SM. Inputs MUST be tf32-rounded fp32. C[M,N] = alpha*A@B^T (+R).
// Modes: PLAIN / ROUND / SILU / ROPE. Optional split-K (SK in {1,4}).
// ---------------------------------------------------------------------------
#define MODE_PLAIN 0
#define MODE_ROUND 1
#define MODE_SILU  2
#define MODE_ROPE  3

#define BM 128
#define BN 128
#define BK 16
#define RS 20
#define STG_F   (2 * 128 * RS)
#define B_F     (128 * RS)
#define STAGES  3
#define GEMM_SMEM (STAGES * STG_F * 4)    // 61440

template<int MODE>
__global__ __launch_bounds__(128, 3)
void tf32_gemm(const float* __restrict__ A, int lda, long long sAz,
               const float* __restrict__ B, int ldb, long long sBz,
               float* __restrict__ C, int ldc, long long sCz,
               const float* __restrict__ R, int K, float alpha,
               int SK, long long sSkz, float* __restrict__ aux)
{
    extern __shared__ float sm[];
    const uint32_t smb = smem_u32(sm);

    const int tid  = threadIdx.x;
    const int warp = tid >> 5, lane = tid & 31;
    const int wm = warp & 1;
    const int wn = warp >> 1;
    const int g  = lane >> 2;
    const int tg = lane & 3;

    int bzr = blockIdx.z;
    int sk = 0;
    if (SK > 1) { sk = bzr % SK; bzr /= SK; }
    const long long bz = bzr;
    A += bz * sAz + (long long)sk * K;
    B += bz * sBz + (long long)sk * K;
    C += bz * sCz + (long long)sk * sSkz;
    const float* Rp = R ? (R + bz * sCz) : nullptr;
    const int row0 = blockIdx.y * BM;
    const int col0 = blockIdx.x * BN;

    auto fill = [&](int st, int k0) {
        uint32_t base = smb + st * (STG_F * 4);
#pragma unroll
        for (int j = 0; j < 8; j++) {
            int id = tid + 128 * j;           // 0..1023
            int isB = id >> 9;
            int r  = (id & 511) >> 2;         // 0..127
            int kc = id & 3;
            long long srow;
            if (isB) {
                int n = col0 + r;
                if (MODE == MODE_SILU) {
                    srow = (n >> 1) + (n & 1) * FFDIM;
                } else if (MODE == MODE_ROPE) {
                    if (n < 2048) {
                        int m = n & 1023;
                        srow = (n & 1024) + (m >> 1) + (m & 1) * 512;
                    } else srow = n;
                } else srow = n;
            } else srow = row0 + r;
            const float* src = (isB ? B + srow * ldb : A + srow * lda) + k0 + kc * 4;
            uint32_t dst = base + (isB ? B_F * 4 : 0) + r * (RS * 4) + kc * 16;
            CP_ASYNC16(dst, src);
        }
    };

    float acc[4][8][4];
#pragma unroll
    for (int mi = 0; mi < 4; mi++)
#pragma unroll
        for (int ni = 0; ni < 8; ni++)
#pragma unroll
            for (int j = 0; j < 4; j++) acc[mi][ni][j] = 0.0f;

    const int NK = K / BK;
    fill(0, 0);       CP_COMMIT();
    fill(1, BK);      CP_COMMIT();

    int st = 0;
    for (int it = 0; it < NK; it++) {
        CP_WAIT(1);
        __syncthreads();

        const float* sA = sm + st * STG_F;
        const float* sB = sA + B_F;
#pragma unroll
        for (int kk = 0; kk < BK; kk += 8) {
            uint32_t af[4][4], bf[8][2];
#pragma unroll
            for (int mi = 0; mi < 4; mi++) {
                int r = wm * 64 + mi * 16 + g;
                af[mi][0] = __float_as_uint(sA[r * RS + kk + tg]);
                af[mi][1] = __float_as_uint(sA[(r + 8) * RS + kk + tg]);
                af[mi][2] = __float_as_uint(sA[r * RS + kk + tg + 4]);
                af[mi][3] = __float_as_uint(sA[(r + 8) * RS + kk + tg + 4]);
            }
#pragma unroll
            for (int ni = 0; ni < 8; ni++) {
                int c = wn * 64 + ni * 8 + g;
                bf[ni][0] = __float_as_uint(sB[c * RS + kk + tg]);
                bf[ni][1] = __float_as_uint(sB[c * RS + kk + tg + 4]);
            }
#pragma unroll
            for (int mi = 0; mi < 4; mi++)
#pragma unroll
                for (int ni = 0; ni < 8; ni++)
                    mma16n8k8(acc[mi][ni], af[mi], bf[ni]);
        }

        int nf = it + 2;
        if (nf < NK) {
            int fst = st + 2; if (fst >= STAGES) fst -= STAGES;
            fill(fst, nf * BK);
        }
        CP_COMMIT();
        if (++st == STAGES) st = 0;
    }

    // ---- epilogue ----
#pragma unroll
    for (int mi = 0; mi < 4; mi++) {
        long long r = row0 + wm * 64 + mi * 16 + g;
#pragma unroll
        for (int ni = 0; ni < 8; ni++) {
            int c = col0 + wn * 64 + ni * 8 + tg * 2;

            if (MODE == MODE_SILU) {
                int oc = c >> 1;
                float x0 = acc[mi][ni][0], u0 = acc[mi][ni][1];
                float x1 = acc[mi][ni][2], u1 = acc[mi][ni][3];
                C[r * ldc + oc]       = round_tf32(x0 / (1.0f + expf(-x0)) * u0);
                C[(r + 8) * ldc + oc] = round_tf32(x1 / (1.0f + expf(-x1)) * u1);
                continue;
            }

            float2 v0, v1;
            v0.x = acc[mi][ni][0] * alpha;  v0.y = acc[mi][ni][1] * alpha;
            v1.x = acc[mi][ni][2] * alpha;  v1.y = acc[mi][ni][3] * alpha;

            if (MODE == MODE_ROPE) {
                if (c >= 2048) {
                    int d = c - 2048;
                    int b0 = (int)(r >> 10), s0 = (int)(r & 1023);
                    int b1 = (int)((r + 8) >> 10), s1 = (int)((r + 8) & 1023);
                    aux[((long long)b0 * DIM + d) * SEQ + s0]     = round_tf32(v0.x);
                    aux[((long long)b0 * DIM + d + 1) * SEQ + s0] = round_tf32(v0.y);
                    aux[((long long)b1 * DIM + d) * SEQ + s1]     = round_tf32(v1.x);
                    aux[((long long)b1 * DIM + d + 1) * SEQ + s1] = round_tf32(v1.y);
                    continue;
                }
                int jj = (c & 1023) >> 1;
                float freq = exp2f(-13.2877124f * ((float)jj / 512.0f));
                int s0 = (int)(r & 1023), s1 = (int)((r + 8) & 1023);
                float sn, cs;
                sincosf((float)s0 * freq, &sn, &cs);
                float a0 = v0.x * cs - v0.y * sn;
                float b0 = v0.y * cs + v0.x * sn;
                v0.x = a0; v0.y = b0;
                sincosf((float)s1 * freq, &sn, &cs);
                float a1 = v1.x * cs - v1.y * sn;
                float b1 = v1.y * cs + v1.x * sn;
                v1.x = a1; v1.y = b1;
                v0.x = round_tf32(v0.x); v0.y = round_tf32(v0.y);
                v1.x = round_tf32(v1.x); v1.y = round_tf32(v1.y);
            }

            long long i0 = r * (long long)ldc + c;
            long long i1 = (r + 8) * (long long)ldc + c;
            if (Rp) {
                float2 r0 = *(const float2*)(Rp + i0);
                float2 r1 = *(const float2*)(Rp + i1);
                v0.x += r0.x; v0.y += r0.y;
                v1.x += r1.x; v1.y += r1.y;
            }
            if (MODE == MODE_ROUND) {
                v0.x = round_tf32(v0.x); v0.y = round_tf32(v0.y);
                v1.x = round_tf32(v1.x); v1.y = round_tf32(v1.y);
            }
            *(float2*)(C + i0) = v0;
            *(float2*)(C + i1) = v1;
        }
    }
}

// ---------------------------------------------------------------------------
// Split-K reduce (4 partials): out = round(p0+p1+p2+p3 (+ R))
// ---------------------------------------------------------------------------
__global__ void reduce_round_kernel(const float* __restrict__ part, long long skStride,
                                    const float* __restrict__ R, float* __restrict__ out)
{
    long long i = ((long long)blockIdx.x * 256 + threadIdx.x) * 4;
    float4 p0 = *(const float4*)(part + i);
    float4 p1 = *(const float4*)(part + skStride + i);
    float4 p2 = *(const float4*)(part + 2 * skStride + i);
    float4 p3 = *(const float4*)(part + 3 * skStride + i);
    float4 v;
    v.x = (p0.x + p1.x) + (p2.x + p3.x);
    v.y = (p0.y + p1.y) + (p2.y + p3.y);
    v.z = (p0.z + p1.z) + (p2.z + p3.z);
    v.w = (p0.w + p1.w) + (p2.w + p3.w);
    if (R) {
        float4 r4 = *(const float4*)(R + i);
        v.x += r4.x; v.y += r4.y; v.z += r4.z; v.w += r4.w;
    }
    v.x = round_tf32(v.x); v.y = round_tf32(v.y);
    v.z = round_tf32(v.z); v.w = round_tf32(v.w);
    *(float4*)(out + i) = v;
}

// ---------------------------------------------------------------------------
// Aux kernels
// ---------------------------------------------------------------------------
__global__ void round_weights_kernel(const float* __restrict__ src,
                                     float* __restrict__ dst)
{
    long long i = ((long long)blockIdx.x * 256 + threadIdx.x) * 4;
    float4 v = *(const float4*)(src + i);
    v.x = round_tf32(v.x); v.y = round_tf32(v.y);
    v.z = round_tf32(v.z); v.w = round_tf32(v.w);
    *(float4*)(dst + i) = v;
}

__global__ void embed_kernel(const int* __restrict__ ids,
                             const float* __restrict__ embed, float* __restrict__ h)
{
    int bs = blockIdx.x;
    long long tok = ids[bs];
    const float4* src = (const float4*)(embed + tok * DIM);
    float4 v = src[threadIdx.x];
    v.x = round_tf32(v.x); v.y = round_tf32(v.y);
    v.z = round_tf32(v.z); v.w = round_tf32(v.w);
    ((float4*)(h + (long long)bs * DIM))[threadIdx.x] = v;
}

// softmax over (p0+p1+p2+p3)*scale rows; writes rounded probs
__global__ void softmax_split_kernel(const float* __restrict__ part, long long skStride,
                                     float* __restrict__ Sm, float scale)
{
    __shared__ float red[256];
    long long row = blockIdx.x;
    const float* r0 = part + row * SEQ;
    int t = threadIdx.x;
    float4 a = ((const float4*)r0)[t];
    float4 b = ((const float4*)(r0 + skStride))[t];
    float4 c = ((const float4*)(r0 + 2 * skStride))[t];
    float4 d = ((const float4*)(r0 + 3 * skStride))[t];
    float4 v;
    v.x = ((a.x + b.x) + (c.x + d.x)) * scale;
    v.y = ((a.y + b.y) + (c.y + d.y)) * scale;
    v.z = ((a.z + b.z) + (c.z + d.z)) * scale;
    v.w = ((a.w + b.w) + (c.w + d.w)) * scale;

    float m = fmaxf(fmaxf(v.x, v.y), fmaxf(v.z, v.w));
    red[t] = m; __syncthreads();
    for (int w = 128; w > 0; w >>= 1) { if (t < w) red[t] = fmaxf(red[t], red[t + w]); __syncthreads(); }
    m = red[0]; __syncthreads();
    float e0 = expf(v.x - m), e1 = expf(v.y - m), e2 = expf(v.z - m), e3 = expf(v.w - m);
    red[t] = e0 + e1 + e2 + e3; __syncthreads();
    for (int w = 128; w > 0; w >>= 1) { if (t < w) red[t] += red[t + w]; __syncthreads(); }
    float inv = 1.0f / red[0];
    float* out = Sm + row * SEQ;
    ((float4*)out)[t] = make_float4(round_tf32(e0 * inv), round_tf32(e1 * inv),
                                    round_tf32(e2 * inv), round_tf32(e3 * inv));
}

// ---------------------------------------------------------------------------
// Host side
// ---------------------------------------------------------------------------
template<int MODE>
static void gemm(const float* A, int lda, long long sAz,
                 const float* B, int ldb, long long sBz,
                 float* C, int ldc, long long sCz,
                 const float* R, int M, int N, int K, float alpha, int bz,
                 int SK = 1, long long sSkz = 0, float* aux = nullptr)
{
    dim3 grid(N / BN, M / BM, bz * SK);
    tf32_gemm<MODE><<<grid, 128, GEMM_SMEM>>>(A, lda, sAz, B, ldb, sBz,
                                              C, ldc, sCz, R, K / SK, alpha,
                                              SK, sSkz, aux);
}

extern "C" void kernel_launch(void* const* d_in, const int* in_sizes, int n_in,
                              void* d_out, int out_size)
{
    (void)in_sizes; (void)n_in; (void)out_size;
    const int*   ids    = (const int*)d_in[0];
    const float* blocks = (const float*)d_in[1];
    float*       out    = (float*)d_out;

    static int attr_done = 0;
    if (!attr_done) {
        cudaFuncSetAttribute(tf32_gemm<MODE_PLAIN>,
                             cudaFuncAttributeMaxDynamicSharedMemorySize, GEMM_SMEM);
        cudaFuncSetAttribute(tf32_gemm<MODE_ROUND>,
                             cudaFuncAttributeMaxDynamicSharedMemorySize, GEMM_SMEM);
        cudaFuncSetAttribute(tf32_gemm<MODE_SILU>,
                             cudaFuncAttributeMaxDynamicSharedMemorySize, GEMM_SMEM);
        cudaFuncSetAttribute(tf32_gemm<MODE_ROPE>,
                             cudaFuncAttributeMaxDynamicSharedMemorySize, GEMM_SMEM);
        attr_done = 1;
    }

    float *w, *h, *qkv, *vt, *s, *a, *t, *part;
    cudaGetSymbolAddress((void**)&w,    g_w);
    cudaGetSymbolAddress((void**)&h,    g_h);
    cudaGetSymbolAddress((void**)&qkv,  g_qkv);
    cudaGetSymbolAddress((void**)&vt,   g_vt);
    cudaGetSymbolAddress((void**)&s,    g_s);
    cudaGetSymbolAddress((void**)&a,    g_a);
    cudaGetSymbolAddress((void**)&t,    g_t);
    cudaGetSymbolAddress((void**)&part, g_part);

    const long long SD3 = (long long)SEQ * 3072;
    const long long SD  = (long long)SEQ * DIM;
    const long long SS  = (long long)SEQ * SEQ;
    const long long SKS_S = (long long)BATCH * SS;   // scores partial stride
    const long long SKS_D = (long long)MTOK * DIM;   // dim-output partial stride
    const int RED_GRID  = (int)(SKS_D / 4 / 256);

    round_weights_kernel<<<(int)(NWEIGHT / 4 / 256), 256>>>(blocks + LAYER0_OFF, w);
    embed_kernel<<<MTOK, 256>>>(ids, blocks, h);

    for (int l = 0; l < 2; l++) {
        const float* Wqkv = w + (long long)l * LAYER_STRIDE;
        const float* Wo   = Wqkv + 3LL * DIM * DIM;
        const float* Wgu  = Wo + (long long)DIM * DIM;
        const float* Wd   = Wgu + 2LL * FFDIM * DIM;

        // qkv: q,k -> qkv (roped+rounded); v -> vt (rounded, transposed)
        gemm<MODE_ROPE>(h, DIM, 0, Wqkv, DIM, 0, qkv, 3 * DIM, 0, nullptr,
                        MTOK, 3 * DIM, DIM, 1.0f, 1, 1, 0, vt);
        // scores partial = q @ k^T (split-K=4); softmax fuses reduce+scale
        gemm<MODE_PLAIN>(qkv, 3 * DIM, SD3, qkv + 1024, 3 * DIM, SD3,
                         part, SEQ, SS, nullptr, SEQ, SEQ, DIM, 1.0f, BATCH,
                         4, SKS_S);
        softmax_split_kernel<<<BATCH * SEQ, 256>>>(part, SKS_S, s, 1.0f / 32.0f);
        // a = attn @ V (split-K=4 + reduce)
        gemm<MODE_PLAIN>(s, SEQ, SS, vt, SEQ, SD, part, DIM, SD, nullptr,
                         SEQ, DIM, SEQ, 1.0f, BATCH, 4, SKS_D);
        reduce_round_kernel<<<RED_GRID, 256>>>(part, SKS_D, nullptr, a);
        // h = a @ Wo^T + h (split-K=4 + reduce w/ residual)
        gemm<MODE_PLAIN>(a, DIM, 0, Wo, DIM, 0, part, DIM, 0, nullptr,
                         MTOK, DIM, DIM, 1.0f, 1, 4, SKS_D);
        reduce_round_kernel<<<RED_GRID, 256>>>(part, SKS_D, h, h);
        // t = silu(h@Wg^T) * (h@Wu^T)
        gemm<MODE_SILU>(h, DIM, 0, Wgu, DIM, 0, t, FFDIM, 0, nullptr,
                        MTOK, 2 * FFDIM, DIM, 1.0f, 1);
        // h = t @ Wd^T + h (split-K=4 + reduce w/ residual)
        gemm<MODE_PLAIN>(t, FFDIM, 0, Wd, FFDIM, 0, part, DIM, 0, nullptr,
                         MTOK, DIM, FFDIM, 1.0f, 1, 4, SKS_D);
        reduce_round_kernel<<<RED_GRID, 256>>>(part, SKS_D, h, h);
    }

    gemm<MODE_PLAIN>(h, DIM, 0, w + 2 * LAYER_STRIDE, DIM, 0, out, VOC, 0, nullptr,
                     MTOK, VOC, DIM, 1.0f, 1);
}

// round 13
// speedup vs baseline: 1.6208x; 1.6208x over previous
#include <cuda_runtime.h>
#include <cuda_fp16.h>
#include <math.h>
#include <stdint.h>

// ---------------------------------------------------------------------------
// Model dims
// ---------------------------------------------------------------------------
#define DIM   1024
#define FFDIM 4096
#define VOC   32000
#define SEQ   1024
#define BATCH 2
#define MTOK  (BATCH * SEQ)

#define LAYER0_OFF   32768000LL
#define LAYER_STRIDE 16777216LL
#define NWEIGHT      (2 * LAYER_STRIDE + (long long)VOC * DIM)

// ---------------------------------------------------------------------------
// Scratch (activations + weights in fp16; split-K partials + logits fp32)
// ---------------------------------------------------------------------------
__device__ __half g_w  [NWEIGHT];
__device__ __half g_h  [MTOK * DIM];
__device__ __half g_qkv[MTOK * 3 * DIM];     // q,k pair-interleaved; v unused
__device__ __half g_vt [BATCH * DIM * SEQ];
__device__ __half g_s  [BATCH * SEQ * SEQ];
__device__ __half g_a  [MTOK * DIM];
__device__ __half g_t  [MTOK * FFDIM];
__device__ float  g_part[2LL * BATCH * SEQ * SEQ];  // 2 split-K slices

// ---------------------------------------------------------------------------
// helpers
// ---------------------------------------------------------------------------
__device__ __forceinline__ uint32_t smem_u32(const void* p) {
    uint32_t a;
    asm("{ .reg .u64 t; cvta.to.shared.u64 t, %1; cvt.u32.u64 %0, t; }" : "=r"(a) : "l"(p));
    return a;
}
#define CP_ASYNC16(dst, src) \
    asm volatile("cp.async.cg.shared.global [%0], [%1], 16;" :: "r"(dst), "l"(src))
#define CP_COMMIT() asm volatile("cp.async.commit_group;" ::: "memory")
#define CP_WAIT(n)  asm volatile("cp.async.wait_group %0;" :: "n"(n) : "memory")

__device__ __forceinline__ void mma16n8k16(float c[4], const uint32_t a[4],
                                           const uint32_t b[2]) {
    asm volatile(
        "mma.sync.aligned.m16n8k16.row.col.f32.f16.f16.f32 "
        "{%0,%1,%2,%3}, {%4,%5,%6,%7}, {%8,%9}, {%0,%1,%2,%3};"
        : "+f"(c[0]), "+f"(c[1]), "+f"(c[2]), "+f"(c[3])
        : "r"(a[0]), "r"(a[1]), "r"(a[2]), "r"(a[3]), "r"(b[0]), "r"(b[1]));
}

// ---------------------------------------------------------------------------
// fp16 GEMM (fp32 accum), cp.async 3-stage, 128 thr, 4 warps (2Mx2N),
// warp tile 64x64, 3 CTAs/SM. C[M,N] = alpha*A@B^T. Modes:
//   PLAIN: C fp32 (split-K partials / logits)
//   SILU : B rows interleaved gate/up; C fp16 silu(g)*u, N/2 cols
//   ROPE : B = Wqkv pair-interleaved; q,k roped -> C fp16; v -> aux transposed
// Optional split-K (SK in {1,2}).
// ---------------------------------------------------------------------------
#define MODE_PLAIN 0
#define MODE_SILU  2
#define MODE_ROPE  3

#define BM 128
#define BN 128
#define BK 16
#define RSH 24                         // halves per smem row (48 B)
#define STG_H   (2 * 128 * RSH)        // halves per stage (A then B)
#define B_H     (128 * RSH)
#define STAGES  3
#define GEMM_SMEM (STAGES * STG_H * 2) // 36864 bytes

template<int MODE>
__global__ __launch_bounds__(128, 3)
void h_gemm(const __half* __restrict__ A, int lda, long long sAz,
            const __half* __restrict__ B, int ldb, long long sBz,
            void* __restrict__ Cv, int ldc, long long sCz,
            int K, float alpha, int SK, long long sSkz,
            __half* __restrict__ aux)
{
    extern __shared__ __half smh[];
    const uint32_t smb = smem_u32(smh);

    const int tid  = threadIdx.x;
    const int warp = tid >> 5, lane = tid & 31;
    const int wm = warp & 1;
    const int wn = warp >> 1;
    const int g  = lane >> 2;
    const int tg = lane & 3;

    int bzr = blockIdx.z;
    int sk = 0;
    if (SK > 1) { sk = bzr & 1; bzr >>= 1; }
    const long long bz = bzr;
    A += bz * sAz + (long long)sk * K;
    B += bz * sBz + (long long)sk * K;
    const int row0 = blockIdx.y * BM;
    const int col0 = blockIdx.x * BN;

    auto fill = [&](int st, int k0) {
        uint32_t base = smb + st * (STG_H * 2);
#pragma unroll
        for (int j = 0; j < 4; j++) {
            int id = tid + 128 * j;           // 0..511
            int isB = id >> 8;
            int r  = (id & 255) >> 1;         // 0..127
            int kc = id & 1;                  // 16B chunk (8 halves)
            long long srow;
            if (isB) {
                int n = col0 + r;
                if (MODE == MODE_SILU) {
                    srow = (n >> 1) + (n & 1) * FFDIM;
                } else if (MODE == MODE_ROPE) {
                    if (n < 2048) {
                        int m = n & 1023;
                        srow = (n & 1024) + (m >> 1) + (m & 1) * 512;
                    } else srow = n;
                } else srow = n;
            } else srow = row0 + r;
            const __half* src = (isB ? B + srow * ldb : A + srow * lda) + k0 + kc * 8;
            uint32_t dst = base + (isB ? B_H * 2 : 0) + r * (RSH * 2) + kc * 16;
            CP_ASYNC16(dst, src);
        }
    };

    float acc[4][8][4];
#pragma unroll
    for (int mi = 0; mi < 4; mi++)
#pragma unroll
        for (int ni = 0; ni < 8; ni++)
#pragma unroll
            for (int j = 0; j < 4; j++) acc[mi][ni][j] = 0.0f;

    const int NK = K / BK;
    fill(0, 0);       CP_COMMIT();
    fill(1, BK);      CP_COMMIT();

    int st = 0;
    for (int it = 0; it < NK; it++) {
        CP_WAIT(1);
        __syncthreads();

        const __half* sA = smh + st * STG_H;
        const __half* sB = sA + B_H;
        {
            uint32_t af[4][4], bf[8][2];
#pragma unroll
            for (int mi = 0; mi < 4; mi++) {
                int r = wm * 64 + mi * 16 + g;
                af[mi][0] = *(const uint32_t*)(sA + r * RSH + 2 * tg);
                af[mi][1] = *(const uint32_t*)(sA + (r + 8) * RSH + 2 * tg);
                af[mi][2] = *(const uint32_t*)(sA + r * RSH + 2 * tg + 8);
                af[mi][3] = *(const uint32_t*)(sA + (r + 8) * RSH + 2 * tg + 8);
            }
#pragma unroll
            for (int ni = 0; ni < 8; ni++) {
                int c = wn * 64 + ni * 8 + g;
                bf[ni][0] = *(const uint32_t*)(sB + c * RSH + 2 * tg);
                bf[ni][1] = *(const uint32_t*)(sB + c * RSH + 2 * tg + 8);
            }
#pragma unroll
            for (int mi = 0; mi < 4; mi++)
#pragma unroll
                for (int ni = 0; ni < 8; ni++)
                    mma16n8k16(acc[mi][ni], af[mi], bf[ni]);
        }

        int nf = it + 2;
        if (nf < NK) {
            int fst = st + 2; if (fst >= STAGES) fst -= STAGES;
            fill(fst, nf * BK);
        }
        CP_COMMIT();
        if (++st == STAGES) st = 0;
    }

    // ---- epilogue ----
#pragma unroll
    for (int mi = 0; mi < 4; mi++) {
        long long r = row0 + wm * 64 + mi * 16 + g;
#pragma unroll
        for (int ni = 0; ni < 8; ni++) {
            int c = col0 + wn * 64 + ni * 8 + tg * 2;

            if (MODE == MODE_PLAIN) {
                float* C = (float*)Cv + bz * sCz + (long long)sk * sSkz;
                float2 v0, v1;
                v0.x = acc[mi][ni][0] * alpha;  v0.y = acc[mi][ni][1] * alpha;
                v1.x = acc[mi][ni][2] * alpha;  v1.y = acc[mi][ni][3] * alpha;
                *(float2*)(C + r * (long long)ldc + c)       = v0;
                *(float2*)(C + (r + 8) * (long long)ldc + c) = v1;
                continue;
            }

            if (MODE == MODE_SILU) {
                __half* C = (__half*)Cv + bz * sCz;
                int oc = c >> 1;
                float x0 = acc[mi][ni][0], u0 = acc[mi][ni][1];
                float x1 = acc[mi][ni][2], u1 = acc[mi][ni][3];
                C[r * ldc + oc]       = __float2half_rn(x0 / (1.0f + expf(-x0)) * u0);
                C[(r + 8) * ldc + oc] = __float2half_rn(x1 / (1.0f + expf(-x1)) * u1);
                continue;
            }

            // MODE_ROPE
            {
                float2 v0, v1;
                v0.x = acc[mi][ni][0];  v0.y = acc[mi][ni][1];
                v1.x = acc[mi][ni][2];  v1.y = acc[mi][ni][3];
                if (c >= 2048) {
                    int d = c - 2048;
                    int b0 = (int)(r >> 10), s0 = (int)(r & 1023);
                    int b1 = (int)((r + 8) >> 10), s1 = (int)((r + 8) & 1023);
                    aux[((long long)b0 * DIM + d) * SEQ + s0]     = __float2half_rn(v0.x);
                    aux[((long long)b0 * DIM + d + 1) * SEQ + s0] = __float2half_rn(v0.y);
                    aux[((long long)b1 * DIM + d) * SEQ + s1]     = __float2half_rn(v1.x);
                    aux[((long long)b1 * DIM + d + 1) * SEQ + s1] = __float2half_rn(v1.y);
                    continue;
                }
                int jj = (c & 1023) >> 1;
                float freq = exp2f(-13.2877124f * ((float)jj / 512.0f));
                int s0 = (int)(r & 1023), s1 = (int)((r + 8) & 1023);
                float sn, cs;
                sincosf((float)s0 * freq, &sn, &cs);
                float a0 = v0.x * cs - v0.y * sn;
                float b0 = v0.y * cs + v0.x * sn;
                sincosf((float)s1 * freq, &sn, &cs);
                float a1 = v1.x * cs - v1.y * sn;
                float b1 = v1.y * cs + v1.x * sn;
                __half* C = (__half*)Cv;
                *(__half2*)(C + r * (long long)ldc + c) =
                    __floats2half2_rn(a0, b0);
                *(__half2*)(C + (r + 8) * (long long)ldc + c) =
                    __floats2half2_rn(a1, b1);
            }
        }
    }
}

// ---------------------------------------------------------------------------
// Split-K reduce: out(fp16) = p0 + p1 (+ R fp16)
// ---------------------------------------------------------------------------
__global__ void reduce_kernel(const float* __restrict__ part, long long skStride,
                              const __half* __restrict__ R, __half* __restrict__ out)
{
    long long i = ((long long)blockIdx.x * 256 + threadIdx.x) * 4;
    float4 p0 = *(const float4*)(part + i);
    float4 p1 = *(const float4*)(part + skStride + i);
    float vx = p0.x + p1.x, vy = p0.y + p1.y;
    float vz = p0.z + p1.z, vw = p0.w + p1.w;
    if (R) {
        __half2 r0 = *(const __half2*)(R + i);
        __half2 r1 = *(const __half2*)(R + i + 2);
        vx += __half2float(r0.x); vy += __half2float(r0.y);
        vz += __half2float(r1.x); vw += __half2float(r1.y);
    }
    __half2* o = (__half2*)(out + i);
    o[0] = __floats2half2_rn(vx, vy);
    o[1] = __floats2half2_rn(vz, vw);
}

// ---------------------------------------------------------------------------
// Aux kernels
// ---------------------------------------------------------------------------
__global__ void convert_weights_kernel(const float* __restrict__ src,
                                       __half* __restrict__ dst)
{
    long long i = ((long long)blockIdx.x * 256 + threadIdx.x) * 4;
    float4 v = *(const float4*)(src + i);
    __half2* o = (__half2*)(dst + i);
    o[0] = __floats2half2_rn(v.x, v.y);
    o[1] = __floats2half2_rn(v.z, v.w);
}

__global__ void embed_kernel(const int* __restrict__ ids,
                             const float* __restrict__ embed, __half* __restrict__ h)
{
    int bs = blockIdx.x;
    long long tok = ids[bs];
    const float4* src = (const float4*)(embed + tok * DIM);
    float4 v = src[threadIdx.x];
    __half2* o = (__half2*)(h + (long long)bs * DIM + threadIdx.x * 4);
    o[0] = __floats2half2_rn(v.x, v.y);
    o[1] = __floats2half2_rn(v.z, v.w);
}

// softmax over (p0+p1)*scale rows; writes fp16 probs
__global__ void softmax_split_kernel(const float* __restrict__ part, long long skStride,
                                     __half* __restrict__ Sm, float scale)
{
    __shared__ float red[256];
    long long row = blockIdx.x;
    const float* r0 = part + row * SEQ;
    const float* r1 = r0 + skStride;
    int t = threadIdx.x;
    float4 a = ((const float4*)r0)[t];
    float4 b = ((const float4*)r1)[t];
    float4 v;
    v.x = (a.x + b.x) * scale; v.y = (a.y + b.y) * scale;
    v.z = (a.z + b.z) * scale; v.w = (a.w + b.w) * scale;

    float m = fmaxf(fmaxf(v.x, v.y), fmaxf(v.z, v.w));
    red[t] = m; __syncthreads();
    for (int w = 128; w > 0; w >>= 1) { if (t < w) red[t] = fmaxf(red[t], red[t + w]); __syncthreads(); }
    m = red[0]; __syncthreads();
    float e0 = expf(v.x - m), e1 = expf(v.y - m), e2 = expf(v.z - m), e3 = expf(v.w - m);
    red[t] = e0 + e1 + e2 + e3; __syncthreads();
    for (int w = 128; w > 0; w >>= 1) { if (t < w) red[t] += red[t + w]; __syncthreads(); }
    float inv = 1.0f / red[0];
    __half2* o = (__half2*)(Sm + row * SEQ + t * 4);
    o[0] = __floats2half2_rn(e0 * inv, e1 * inv);
    o[1] = __floats2half2_rn(e2 * inv, e3 * inv);
}

// ---------------------------------------------------------------------------
// Host side
// ---------------------------------------------------------------------------
template<int MODE>
static void gemm(const __half* A, int lda, long long sAz,
                 const __half* B, int ldb, long long sBz,
                 void* C, int ldc, long long sCz,
                 int M, int N, int K, float alpha, int bz,
                 int SK = 1, long long sSkz = 0, __half* aux = nullptr)
{
    dim3 grid(N / BN, M / BM, bz * SK);
    h_gemm<MODE><<<grid, 128, GEMM_SMEM>>>(A, lda, sAz, B, ldb, sBz,
                                           C, ldc, sCz, K / SK, alpha,
                                           SK, sSkz, aux);
}

extern "C" void kernel_launch(void* const* d_in, const int* in_sizes, int n_in,
                              void* d_out, int out_size)
{
    (void)in_sizes; (void)n_in; (void)out_size;
    const int*   ids    = (const int*)d_in[0];
    const float* blocks = (const float*)d_in[1];
    float*       out    = (float*)d_out;

    static int attr_done = 0;
    if (!attr_done) {
        cudaFuncSetAttribute(h_gemm<MODE_PLAIN>,
                             cudaFuncAttributeMaxDynamicSharedMemorySize, GEMM_SMEM);
        cudaFuncSetAttribute(h_gemm<MODE_SILU>,
                             cudaFuncAttributeMaxDynamicSharedMemorySize, GEMM_SMEM);
        cudaFuncSetAttribute(h_gemm<MODE_ROPE>,
                             cudaFuncAttributeMaxDynamicSharedMemorySize, GEMM_SMEM);
        attr_done = 1;
    }

    __half *w, *h, *qkv, *vt, *s, *a, *t;
    float *part;
    cudaGetSymbolAddress((void**)&w,    g_w);
    cudaGetSymbolAddress((void**)&h,    g_h);
    cudaGetSymbolAddress((void**)&qkv,  g_qkv);
    cudaGetSymbolAddress((void**)&vt,   g_vt);
    cudaGetSymbolAddress((void**)&s,    g_s);
    cudaGetSymbolAddress((void**)&a,    g_a);
    cudaGetSymbolAddress((void**)&t,    g_t);
    cudaGetSymbolAddress((void**)&part, g_part);

    const long long SD3 = (long long)SEQ * 3072;
    const long long SD  = (long long)SEQ * DIM;
    const long long SS  = (long long)SEQ * SEQ;
    const long long SKS_S = (long long)BATCH * SS;   // scores partial stride
    const long long SKS_D = (long long)MTOK * DIM;   // dim-output partial stride
    const int RED_GRID  = (int)(SKS_D / 4 / 256);

    convert_weights_kernel<<<(int)(NWEIGHT / 4 / 256), 256>>>(blocks + LAYER0_OFF, w);
    embed_kernel<<<MTOK, 256>>>(ids, blocks, h);

    for (int l = 0; l < 2; l++) {
        const __half* Wqkv = w + (long long)l * LAYER_STRIDE;
        const __half* Wo   = Wqkv + 3LL * DIM * DIM;
        const __half* Wgu  = Wo + (long long)DIM * DIM;
        const __half* Wd   = Wgu + 2LL * FFDIM * DIM;

        // qkv: q,k -> qkv (roped); v -> vt (transposed)
        gemm<MODE_ROPE>(h, DIM, 0, Wqkv, DIM, 0, qkv, 3 * DIM, 0,
                        MTOK, 3 * DIM, DIM, 1.0f, 1, 1, 0, vt);
        // scores partial = q @ k^T (split-K=2); softmax fuses reduce+scale
        gemm<MODE_PLAIN>(qkv, 3 * DIM, SD3, qkv + 1024, 3 * DIM, SD3,
                         part, SEQ, SS, SEQ, SEQ, DIM, 1.0f, BATCH, 2, SKS_S);
        softmax_split_kernel<<<BATCH * SEQ, 256>>>(part, SKS_S, s, 1.0f / 32.0f);
        // a = attn @ V (split-K=2 + reduce)
        gemm<MODE_PLAIN>(s, SEQ, SS, vt, SEQ, SD, part, DIM, SD,
                         SEQ, DIM, SEQ, 1.0f, BATCH, 2, SKS_D);
        reduce_kernel<<<RED_GRID, 256>>>(part, SKS_D, nullptr, a);
        // h = a @ Wo^T + h (split-K=2 + reduce w/ residual)
        gemm<MODE_PLAIN>(a, DIM, 0, Wo, DIM, 0, part, DIM, 0,
                         MTOK, DIM, DIM, 1.0f, 1, 2, SKS_D);
        reduce_kernel<<<RED_GRID, 256>>>(part, SKS_D, h, h);
        // t = silu(h@Wg^T) * (h@Wu^T)
        gemm<MODE_SILU>(h, DIM, 0, Wgu, DIM, 0, t, FFDIM, 0,
                        MTOK, 2 * FFDIM, DIM, 1.0f, 1);
        // h = t @ Wd^T + h (split-K=2 + reduce w/ residual)
        gemm<MODE_PLAIN>(t, FFDIM, 0, Wd, FFDIM, 0, part, DIM, 0,
                         MTOK, DIM, FFDIM, 1.0f, 1, 2, SKS_D);
        reduce_kernel<<<RED_GRID, 256>>>(part, SKS_D, h, h);
    }

    gemm<MODE_PLAIN>(h, DIM, 0, w + 2 * LAYER_STRIDE, DIM, 0, out, VOC, 0,
                     MTOK, VOC, DIM, 1.0f, 1);
}

// round 14
// speedup vs baseline: 1.8221x; 1.1242x over previous
#include <cuda_runtime.h>
#include <cuda_fp16.h>
#include <math.h>
#include <stdint.h>

// ---------------------------------------------------------------------------
// Model dims
// ---------------------------------------------------------------------------
#define DIM   1024
#define FFDIM 4096
#define VOC   32000
#define SEQ   1024
#define BATCH 2
#define MTOK  (BATCH * SEQ)

#define LAYER0_OFF   32768000LL
#define LAYER_STRIDE 16777216LL
#define NWEIGHT      (2 * LAYER_STRIDE + (long long)VOC * DIM)

// ---------------------------------------------------------------------------
// Scratch (activations + weights fp16; split-K partials + logits fp32)
// ---------------------------------------------------------------------------
__device__ __half g_w  [NWEIGHT];
__device__ __half g_h  [MTOK * DIM];
__device__ __half g_qkv[MTOK * 3 * DIM];     // q,k pair-interleaved; v unused
__device__ __half g_vt [BATCH * DIM * SEQ];
__device__ __half g_s  [BATCH * SEQ * SEQ];
__device__ __half g_a  [MTOK * DIM];
__device__ __half g_t  [MTOK * FFDIM];
__device__ float  g_part[2LL * BATCH * SEQ * SEQ];  // 2 split-K slices

// ---------------------------------------------------------------------------
// helpers
// ---------------------------------------------------------------------------
__device__ __forceinline__ uint32_t smem_u32(const void* p) {
    uint32_t a;
    asm("{ .reg .u64 t; cvta.to.shared.u64 t, %1; cvt.u32.u64 %0, t; }" : "=r"(a) : "l"(p));
    return a;
}
#define CP_ASYNC16(dst, src) \
    asm volatile("cp.async.cg.shared.global [%0], [%1], 16;" :: "r"(dst), "l"(src))
#define CP_COMMIT() asm volatile("cp.async.commit_group;" ::: "memory")
#define CP_WAIT(n)  asm volatile("cp.async.wait_group %0;" :: "n"(n) : "memory")

__device__ __forceinline__ void mma16n8k16(float c[4], const uint32_t a[4],
                                           const uint32_t b[2]) {
    asm volatile(
        "mma.sync.aligned.m16n8k16.row.col.f32.f16.f16.f32 "
        "{%0,%1,%2,%3}, {%4,%5,%6,%7}, {%8,%9}, {%0,%1,%2,%3};"
        : "+f"(c[0]), "+f"(c[1]), "+f"(c[2]), "+f"(c[3])
        : "r"(a[0]), "r"(a[1]), "r"(a[2]), "r"(a[3]), "r"(b[0]), "r"(b[1]));
}

// ---------------------------------------------------------------------------
// fp16 GEMM (fp32 accum), cp.async 3-stage, BK=32, 128 thr, 4 warps (2Mx2N),
// warp tile 64x64, 3 CTAs/SM. C[M,N] = alpha*A@B^T. Modes as before.
// ---------------------------------------------------------------------------
#define MODE_PLAIN 0
#define MODE_SILU  2
#define MODE_ROPE  3

#define BM 128
#define BN 128
#define BK 32
#define RSH 40                         // halves per smem row (80 B)
#define STG_H   (2 * 128 * RSH)        // halves per stage (A then B)
#define B_H     (128 * RSH)
#define STAGES  3
#define GEMM_SMEM (STAGES * STG_H * 2) // 61440 bytes

template<int MODE>
__global__ __launch_bounds__(128, 3)
void h_gemm(const __half* __restrict__ A, int lda, long long sAz,
            const __half* __restrict__ B, int ldb, long long sBz,
            void* __restrict__ Cv, int ldc, long long sCz,
            int K, float alpha, int SK, long long sSkz,
            __half* __restrict__ aux)
{
    extern __shared__ __half smh[];
    const uint32_t smb = smem_u32(smh);

    const int tid  = threadIdx.x;
    const int warp = tid >> 5, lane = tid & 31;
    const int wm = warp & 1;
    const int wn = warp >> 1;
    const int g  = lane >> 2;
    const int tg = lane & 3;

    int bzr = blockIdx.z;
    int sk = 0;
    if (SK > 1) { sk = bzr & 1; bzr >>= 1; }
    const long long bz = bzr;
    A += bz * sAz + (long long)sk * K;
    B += bz * sBz + (long long)sk * K;
    const int row0 = blockIdx.y * BM;
    const int col0 = blockIdx.x * BN;

    auto fill = [&](int st, int k0) {
        uint32_t base = smb + st * (STG_H * 2);
#pragma unroll
        for (int j = 0; j < 8; j++) {
            int id = tid + 128 * j;           // 0..1023
            int isB = id >> 9;
            int r  = (id & 511) >> 2;         // 0..127
            int kc = id & 3;                  // 16B chunk (8 halves)
            long long srow;
            if (isB) {
                int n = col0 + r;
                if (MODE == MODE_SILU) {
                    srow = (n >> 1) + (n & 1) * FFDIM;
                } else if (MODE == MODE_ROPE) {
                    if (n < 2048) {
                        int m = n & 1023;
                        srow = (n & 1024) + (m >> 1) + (m & 1) * 512;
                    } else srow = n;
                } else srow = n;
            } else srow = row0 + r;
            const __half* src = (isB ? B + srow * ldb : A + srow * lda) + k0 + kc * 8;
            uint32_t dst = base + (isB ? B_H * 2 : 0) + r * (RSH * 2) + kc * 16;
            CP_ASYNC16(dst, src);
        }
    };

    float acc[4][8][4];
#pragma unroll
    for (int mi = 0; mi < 4; mi++)
#pragma unroll
        for (int ni = 0; ni < 8; ni++)
#pragma unroll
            for (int j = 0; j < 4; j++) acc[mi][ni][j] = 0.0f;

    const int NK = K / BK;
    fill(0, 0);       CP_COMMIT();
    fill(1, BK);      CP_COMMIT();

    int st = 0;
    for (int it = 0; it < NK; it++) {
        CP_WAIT(1);
        __syncthreads();

        const __half* sA = smh + st * STG_H;
        const __half* sB = sA + B_H;
#pragma unroll
        for (int kk = 0; kk < BK; kk += 16) {
            uint32_t af[4][4], bf[8][2];
#pragma unroll
            for (int mi = 0; mi < 4; mi++) {
                int r = wm * 64 + mi * 16 + g;
                af[mi][0] = *(const uint32_t*)(sA + r * RSH + kk + 2 * tg);
                af[mi][1] = *(const uint32_t*)(sA + (r + 8) * RSH + kk + 2 * tg);
                af[mi][2] = *(const uint32_t*)(sA + r * RSH + kk + 2 * tg + 8);
                af[mi][3] = *(const uint32_t*)(sA + (r + 8) * RSH + kk + 2 * tg + 8);
            }
#pragma unroll
            for (int ni = 0; ni < 8; ni++) {
                int c = wn * 64 + ni * 8 + g;
                bf[ni][0] = *(const uint32_t*)(sB + c * RSH + kk + 2 * tg);
                bf[ni][1] = *(const uint32_t*)(sB + c * RSH + kk + 2 * tg + 8);
            }
#pragma unroll
            for (int mi = 0; mi < 4; mi++)
#pragma unroll
                for (int ni = 0; ni < 8; ni++)
                    mma16n8k16(acc[mi][ni], af[mi], bf[ni]);
        }

        int nf = it + 2;
        if (nf < NK) {
            int fst = st + 2; if (fst >= STAGES) fst -= STAGES;
            fill(fst, nf * BK);
        }
        CP_COMMIT();
        if (++st == STAGES) st = 0;
    }

    // ---- epilogue ----
#pragma unroll
    for (int mi = 0; mi < 4; mi++) {
        long long r = row0 + wm * 64 + mi * 16 + g;
#pragma unroll
        for (int ni = 0; ni < 8; ni++) {
            int c = col0 + wn * 64 + ni * 8 + tg * 2;

            if (MODE == MODE_PLAIN) {
                float* C = (float*)Cv + bz * sCz + (long long)sk * sSkz;
                float2 v0, v1;
                v0.x = acc[mi][ni][0] * alpha;  v0.y = acc[mi][ni][1] * alpha;
                v1.x = acc[mi][ni][2] * alpha;  v1.y = acc[mi][ni][3] * alpha;
                *(float2*)(C + r * (long long)ldc + c)       = v0;
                *(float2*)(C + (r + 8) * (long long)ldc + c) = v1;
                continue;
            }

            if (MODE == MODE_SILU) {
                __half* C = (__half*)Cv + bz * sCz;
                int oc = c >> 1;
                float x0 = acc[mi][ni][0], u0 = acc[mi][ni][1];
                float x1 = acc[mi][ni][2], u1 = acc[mi][ni][3];
                C[r * ldc + oc]       = __float2half_rn(x0 / (1.0f + expf(-x0)) * u0);
                C[(r + 8) * ldc + oc] = __float2half_rn(x1 / (1.0f + expf(-x1)) * u1);
                continue;
            }

            // MODE_ROPE
            {
                float2 v0, v1;
                v0.x = acc[mi][ni][0];  v0.y = acc[mi][ni][1];
                v1.x = acc[mi][ni][2];  v1.y = acc[mi][ni][3];
                if (c >= 2048) {
                    int d = c - 2048;
                    int b0 = (int)(r >> 10), s0 = (int)(r & 1023);
                    int b1 = (int)((r + 8) >> 10), s1 = (int)((r + 8) & 1023);
                    aux[((long long)b0 * DIM + d) * SEQ + s0]     = __float2half_rn(v0.x);
                    aux[((long long)b0 * DIM + d + 1) * SEQ + s0] = __float2half_rn(v0.y);
                    aux[((long long)b1 * DIM + d) * SEQ + s1]     = __float2half_rn(v1.x);
                    aux[((long long)b1 * DIM + d + 1) * SEQ + s1] = __float2half_rn(v1.y);
                    continue;
                }
                int jj = (c & 1023) >> 1;
                float freq = exp2f(-13.2877124f * ((float)jj / 512.0f));
                int s0 = (int)(r & 1023), s1 = (int)((r + 8) & 1023);
                float sn, cs;
                sincosf((float)s0 * freq, &sn, &cs);
                float a0 = v0.x * cs - v0.y * sn;
                float b0 = v0.y * cs + v0.x * sn;
                sincosf((float)s1 * freq, &sn, &cs);
                float a1 = v1.x * cs - v1.y * sn;
                float b1 = v1.y * cs + v1.x * sn;
                __half* C = (__half*)Cv;
                *(__half2*)(C + r * (long long)ldc + c) =
                    __floats2half2_rn(a0, b0);
                *(__half2*)(C + (r + 8) * (long long)ldc + c) =
                    __floats2half2_rn(a1, b1);
            }
        }
    }
}

// ---------------------------------------------------------------------------
// Split-K reduce: out(fp16) = p0 + p1 (+ R fp16)
// ---------------------------------------------------------------------------
__global__ void reduce_kernel(const float* __restrict__ part, long long skStride,
                              const __half* __restrict__ R, __half* __restrict__ out)
{
    long long i = ((long long)blockIdx.x * 256 + threadIdx.x) * 4;
    float4 p0 = *(const float4*)(part + i);
    float4 p1 = *(const float4*)(part + skStride + i);
    float vx = p0.x + p1.x, vy = p0.y + p1.y;
    float vz = p0.z + p1.z, vw = p0.w + p1.w;
    if (R) {
        __half2 r0 = *(const __half2*)(R + i);
        __half2 r1 = *(const __half2*)(R + i + 2);
        vx += __half2float(r0.x); vy += __half2float(r0.y);
        vz += __half2float(r1.x); vw += __half2float(r1.y);
    }
    __half2* o = (__half2*)(out + i);
    o[0] = __floats2half2_rn(vx, vy);
    o[1] = __floats2half2_rn(vz, vw);
}

// ---------------------------------------------------------------------------
// Aux kernels
// ---------------------------------------------------------------------------
__global__ void convert_weights_kernel(const float* __restrict__ src,
                                       __half* __restrict__ dst)
{
    long long i = ((long long)blockIdx.x * 256 + threadIdx.x) * 4;
    float4 v = *(const float4*)(src + i);
    __half2* o = (__half2*)(dst + i);
    o[0] = __floats2half2_rn(v.x, v.y);
    o[1] = __floats2half2_rn(v.z, v.w);
}

__global__ void embed_kernel(const int* __restrict__ ids,
                             const float* __restrict__ embed, __half* __restrict__ h)
{
    int bs = blockIdx.x;
    long long tok = ids[bs];
    const float4* src = (const float4*)(embed + tok * DIM);
    float4 v = src[threadIdx.x];
    __half2* o = (__half2*)(h + (long long)bs * DIM + threadIdx.x * 4);
    o[0] = __floats2half2_rn(v.x, v.y);
    o[1] = __floats2half2_rn(v.z, v.w);
}

// softmax over (p0+p1)*scale rows; writes fp16 probs
__global__ void softmax_split_kernel(const float* __restrict__ part, long long skStride,
                                     __half* __restrict__ Sm, float scale)
{
    __shared__ float red[256];
    long long row = blockIdx.x;
    const float* r0 = part + row * SEQ;
    const float* r1 = r0 + skStride;
    int t = threadIdx.x;
    float4 a = ((const float4*)r0)[t];
    float4 b = ((const float4*)r1)[t];
    float4 v;
    v.x = (a.x + b.x) * scale; v.y = (a.y + b.y) * scale;
    v.z = (a.z + b.z) * scale; v.w = (a.w + b.w) * scale;

    float m = fmaxf(fmaxf(v.x, v.y), fmaxf(v.z, v.w));
    red[t] = m; __syncthreads();
    for (int w = 128; w > 0; w >>= 1) { if (t < w) red[t] = fmaxf(red[t], red[t + w]); __syncthreads(); }
    m = red[0]; __syncthreads();
    float e0 = expf(v.x - m), e1 = expf(v.y - m), e2 = expf(v.z - m), e3 = expf(v.w - m);
    red[t] = e0 + e1 + e2 + e3; __syncthreads();
    for (int w = 128; w > 0; w >>= 1) { if (t < w) red[t] += red[t + w]; __syncthreads(); }
    float inv = 1.0f / red[0];
    __half2* o = (__half2*)(Sm + row * SEQ + t * 4);
    o[0] = __floats2half2_rn(e0 * inv, e1 * inv);
    o[1] = __floats2half2_rn(e2 * inv, e3 * inv);
}

// ---------------------------------------------------------------------------
// Host side
// ---------------------------------------------------------------------------
template<int MODE>
static void gemm(const __half* A, int lda, long long sAz,
                 const __half* B, int ldb, long long sBz,
                 void* C, int ldc, long long sCz,
                 int M, int N, int K, float alpha, int bz,
                 int SK = 1, long long sSkz = 0, __half* aux = nullptr)
{
    dim3 grid(N / BN, M / BM, bz * SK);
    h_gemm<MODE><<<grid, 128, GEMM_SMEM>>>(A, lda, sAz, B, ldb, sBz,
                                           C, ldc, sCz, K / SK, alpha,
                                           SK, sSkz, aux);
}

extern "C" void kernel_launch(void* const* d_in, const int* in_sizes, int n_in,
                              void* d_out, int out_size)
{
    (void)in_sizes; (void)n_in; (void)out_size;
    const int*   ids    = (const int*)d_in[0];
    const float* blocks = (const float*)d_in[1];
    float*       out    = (float*)d_out;

    static int attr_done = 0;
    if (!attr_done) {
        cudaFuncSetAttribute(h_gemm<MODE_PLAIN>,
                             cudaFuncAttributeMaxDynamicSharedMemorySize, GEMM_SMEM);
        cudaFuncSetAttribute(h_gemm<MODE_SILU>,
                             cudaFuncAttributeMaxDynamicSharedMemorySize, GEMM_SMEM);
        cudaFuncSetAttribute(h_gemm<MODE_ROPE>,
                             cudaFuncAttributeMaxDynamicSharedMemorySize, GEMM_SMEM);
        attr_done = 1;
    }

    __half *w, *h, *qkv, *vt, *s, *a, *t;
    float *part;
    cudaGetSymbolAddress((void**)&w,    g_w);
    cudaGetSymbolAddress((void**)&h,    g_h);
    cudaGetSymbolAddress((void**)&qkv,  g_qkv);
    cudaGetSymbolAddress((void**)&vt,   g_vt);
    cudaGetSymbolAddress((void**)&s,    g_s);
    cudaGetSymbolAddress((void**)&a,    g_a);
    cudaGetSymbolAddress((void**)&t,    g_t);
    cudaGetSymbolAddress((void**)&part, g_part);

    const long long SD3 = (long long)SEQ * 3072;
    const long long SD  = (long long)SEQ * DIM;
    const long long SS  = (long long)SEQ * SEQ;
    const long long SKS_S = (long long)BATCH * SS;   // scores partial stride
    const long long SKS_D = (long long)MTOK * DIM;   // dim-output partial stride
    const int RED_GRID  = (int)(SKS_D / 4 / 256);

    convert_weights_kernel<<<(int)(NWEIGHT / 4 / 256), 256>>>(blocks + LAYER0_OFF, w);
    embed_kernel<<<MTOK, 256>>>(ids, blocks, h);

    for (int l = 0; l < 2; l++) {
        const __half* Wqkv = w + (long long)l * LAYER_STRIDE;
        const __half* Wo   = Wqkv + 3LL * DIM * DIM;
        const __half* Wgu  = Wo + (long long)DIM * DIM;
        const __half* Wd   = Wgu + 2LL * FFDIM * DIM;

        // qkv: q,k -> qkv (roped); v -> vt (transposed)
        gemm<MODE_ROPE>(h, DIM, 0, Wqkv, DIM, 0, qkv, 3 * DIM, 0,
                        MTOK, 3 * DIM, DIM, 1.0f, 1, 1, 0, vt);
        // scores partial = q @ k^T (split-K=2); softmax fuses reduce+scale
        gemm<MODE_PLAIN>(qkv, 3 * DIM, SD3, qkv + 1024, 3 * DIM, SD3,
                         part, SEQ, SS, SEQ, SEQ, DIM, 1.0f, BATCH, 2, SKS_S);
        softmax_split_kernel<<<BATCH * SEQ, 256>>>(part, SKS_S, s, 1.0f / 32.0f);
        // a = attn @ V (split-K=2 + reduce)
        gemm<MODE_PLAIN>(s, SEQ, SS, vt, SEQ, SD, part, DIM, SD,
                         SEQ, DIM, SEQ, 1.0f, BATCH, 2, SKS_D);
        reduce_kernel<<<RED_GRID, 256>>>(part, SKS_D, nullptr, a);
        // h = a @ Wo^T + h (split-K=2 + reduce w/ residual)
        gemm<MODE_PLAIN>(a, DIM, 0, Wo, DIM, 0, part, DIM, 0,
                         MTOK, DIM, DIM, 1.0f, 1, 2, SKS_D);
        reduce_kernel<<<RED_GRID, 256>>>(part, SKS_D, h, h);
        // t = silu(h@Wg^T) * (h@Wu^T)
        gemm<MODE_SILU>(h, DIM, 0, Wgu, DIM, 0, t, FFDIM, 0,
                        MTOK, 2 * FFDIM, DIM, 1.0f, 1);
        // h = t @ Wd^T + h (split-K=2 + reduce w/ residual)
        gemm<MODE_PLAIN>(t, FFDIM, 0, Wd, FFDIM, 0, part, DIM, 0,
                         MTOK, DIM, FFDIM, 1.0f, 1, 2, SKS_D);
        reduce_kernel<<<RED_GRID, 256>>>(part, SKS_D, h, h);
    }

    gemm<MODE_PLAIN>(h, DIM, 0, w + 2 * LAYER_STRIDE, DIM, 0, out, VOC, 0,
                     MTOK, VOC, DIM, 1.0f, 1);
}

// round 15
// speedup vs baseline: 1.8387x; 1.0091x over previous
#include <cuda_runtime.h>
#include <cuda_fp16.h>
#include <math.h>
#include <stdint.h>

// ---------------------------------------------------------------------------
// Model dims
// ---------------------------------------------------------------------------
#define DIM   1024
#define FFDIM 4096
#define VOC   32000
#define SEQ   1024
#define BATCH 2
#define MTOK  (BATCH * SEQ)

#define LAYER0_OFF   32768000LL
#define LAYER_STRIDE 16777216LL
#define NWEIGHT      (2 * LAYER_STRIDE + (long long)VOC * DIM)

// ---------------------------------------------------------------------------
// Scratch (activations + weights fp16; split-K partials + logits fp32)
// ---------------------------------------------------------------------------
__device__ __half g_w  [NWEIGHT];
__device__ __half g_h  [MTOK * DIM];
__device__ __half g_qkv[MTOK * 3 * DIM];     // q,k pair-interleaved; v unused
__device__ __half g_vt [BATCH * DIM * SEQ];
__device__ __half g_s  [BATCH * SEQ * SEQ];
__device__ __half g_a  [MTOK * DIM];
__device__ __half g_t  [MTOK * FFDIM];
__device__ float  g_part[2LL * BATCH * SEQ * SEQ];  // 2 split-K slices

// ---------------------------------------------------------------------------
// helpers
// ---------------------------------------------------------------------------
__device__ __forceinline__ uint32_t smem_u32(const void* p) {
    uint32_t a;
    asm("{ .reg .u64 t; cvta.to.shared.u64 t, %1; cvt.u32.u64 %0, t; }" : "=r"(a) : "l"(p));
    return a;
}
#define CP_ASYNC16(dst, src) \
    asm volatile("cp.async.cg.shared.global [%0], [%1], 16;" :: "r"(dst), "l"(src))
#define CP_COMMIT() asm volatile("cp.async.commit_group;" ::: "memory")
#define CP_WAIT(n)  asm volatile("cp.async.wait_group %0;" :: "n"(n) : "memory")

#define LDSM4(r0, r1, r2, r3, addr) \
    asm volatile("ldmatrix.sync.aligned.m8n8.x4.shared.b16 {%0,%1,%2,%3}, [%4];" \
        : "=r"(r0), "=r"(r1), "=r"(r2), "=r"(r3) : "r"(addr))

__device__ __forceinline__ void mma16n8k16(float c[4], const uint32_t a[4],
                                           const uint32_t b[2]) {
    asm volatile(
        "mma.sync.aligned.m16n8k16.row.col.f32.f16.f16.f32 "
        "{%0,%1,%2,%3}, {%4,%5,%6,%7}, {%8,%9}, {%0,%1,%2,%3};"
        : "+f"(c[0]), "+f"(c[1]), "+f"(c[2]), "+f"(c[3])
        : "r"(a[0]), "r"(a[1]), "r"(a[2]), "r"(a[3]), "r"(b[0]), "r"(b[1]));
}

// ---------------------------------------------------------------------------
// fp16 GEMM (fp32 accum), cp.async 3-stage, BK=32, ldmatrix fragment loads,
// 128 thr, 4 warps (2Mx2N), warp tile 64x64, 3 CTAs/SM.
// C[M,N] = alpha*A@B^T. Modes: PLAIN / SILU / ROPE. Optional split-K=2.
// ---------------------------------------------------------------------------
#define MODE_PLAIN 0
#define MODE_SILU  2
#define MODE_ROPE  3

#define BM 128
#define BN 128
#define BK 32
#define RSH 40                         // halves per smem row (80 B)
#define STG_H   (2 * 128 * RSH)        // halves per stage (A then B)
#define B_H     (128 * RSH)
#define STAGES  3
#define GEMM_SMEM (STAGES * STG_H * 2) // 61440 bytes

template<int MODE>
__global__ __launch_bounds__(128, 3)
void h_gemm(const __half* __restrict__ A, int lda, long long sAz,
            const __half* __restrict__ B, int ldb, long long sBz,
            void* __restrict__ Cv, int ldc, long long sCz,
            int K, float alpha, int SK, long long sSkz,
            __half* __restrict__ aux)
{
    extern __shared__ __half smh[];
    const uint32_t smb = smem_u32(smh);

    const int tid  = threadIdx.x;
    const int warp = tid >> 5, lane = tid & 31;
    const int wm = warp & 1;
    const int wn = warp >> 1;
    const int g  = lane >> 2;
    const int tg = lane & 3;

    int bzr = blockIdx.z;
    int sk = 0;
    if (SK > 1) { sk = bzr & 1; bzr >>= 1; }
    const long long bz = bzr;
    A += bz * sAz + (long long)sk * K;
    B += bz * sBz + (long long)sk * K;
    const int row0 = blockIdx.y * BM;
    const int col0 = blockIdx.x * BN;

    // ldmatrix per-lane base offsets (halves within stage)
    uint32_t aoff[4], boff[4];
#pragma unroll
    for (int mi = 0; mi < 4; mi++) {
        int r = wm * 64 + mi * 16 + ((lane >> 3) & 1) * 8 + (lane & 7);
        aoff[mi] = r * RSH + (lane >> 4) * 8;
    }
#pragma unroll
    for (int p = 0; p < 4; p++) {
        int c = wn * 64 + p * 16 + ((lane >> 4) & 1) * 8 + (lane & 7);
        boff[p] = c * RSH + ((lane >> 3) & 1) * 8;
    }

    auto fill = [&](int st, int k0) {
        uint32_t base = smb + st * (STG_H * 2);
#pragma unroll
        for (int j = 0; j < 8; j++) {
            int id = tid + 128 * j;           // 0..1023
            int isB = id >> 9;
            int r  = (id & 511) >> 2;         // 0..127
            int kc = id & 3;                  // 16B chunk (8 halves)
            long long srow;
            if (isB) {
                int n = col0 + r;
                if (MODE == MODE_SILU) {
                    srow = (n >> 1) + (n & 1) * FFDIM;
                } else if (MODE == MODE_ROPE) {
                    if (n < 2048) {
                        int m = n & 1023;
                        srow = (n & 1024) + (m >> 1) + (m & 1) * 512;
                    } else srow = n;
                } else srow = n;
            } else srow = row0 + r;
            const __half* src = (isB ? B + srow * ldb : A + srow * lda) + k0 + kc * 8;
            uint32_t dst = base + (isB ? B_H * 2 : 0) + r * (RSH * 2) + kc * 16;
            CP_ASYNC16(dst, src);
        }
    };

    float acc[4][8][4];
#pragma unroll
    for (int mi = 0; mi < 4; mi++)
#pragma unroll
        for (int ni = 0; ni < 8; ni++)
#pragma unroll
            for (int j = 0; j < 4; j++) acc[mi][ni][j] = 0.0f;

    const int NK = K / BK;
    fill(0, 0);       CP_COMMIT();
    fill(1, BK);      CP_COMMIT();

    int st = 0;
    for (int it = 0; it < NK; it++) {
        CP_WAIT(1);
        __syncthreads();

        const uint32_t stbase = smb + st * (STG_H * 2);
#pragma unroll
        for (int kk = 0; kk < BK; kk += 16) {
            uint32_t af[4][4], bf[8][2];
#pragma unroll
            for (int mi = 0; mi < 4; mi++)
                LDSM4(af[mi][0], af[mi][1], af[mi][2], af[mi][3],
                      stbase + (aoff[mi] + kk) * 2);
#pragma unroll
            for (int p = 0; p < 4; p++)
                LDSM4(bf[2 * p][0], bf[2 * p][1], bf[2 * p + 1][0], bf[2 * p + 1][1],
                      stbase + B_H * 2 + (boff[p] + kk) * 2);
#pragma unroll
            for (int mi = 0; mi < 4; mi++)
#pragma unroll
                for (int ni = 0; ni < 8; ni++)
                    mma16n8k16(acc[mi][ni], af[mi], bf[ni]);
        }

        int nf = it + 2;
        if (nf < NK) {
            int fst = st + 2; if (fst >= STAGES) fst -= STAGES;
            fill(fst, nf * BK);
        }
        CP_COMMIT();
        if (++st == STAGES) st = 0;
    }

    // ---- epilogue ----
#pragma unroll
    for (int mi = 0; mi < 4; mi++) {
        long long r = row0 + wm * 64 + mi * 16 + g;
#pragma unroll
        for (int ni = 0; ni < 8; ni++) {
            int c = col0 + wn * 64 + ni * 8 + tg * 2;

            if (MODE == MODE_PLAIN) {
                float* C = (float*)Cv + bz * sCz + (long long)sk * sSkz;
                float2 v0, v1;
                v0.x = acc[mi][ni][0] * alpha;  v0.y = acc[mi][ni][1] * alpha;
                v1.x = acc[mi][ni][2] * alpha;  v1.y = acc[mi][ni][3] * alpha;
                *(float2*)(C + r * (long long)ldc + c)       = v0;
                *(float2*)(C + (r + 8) * (long long)ldc + c) = v1;
                continue;
            }

            if (MODE == MODE_SILU) {
                __half* C = (__half*)Cv + bz * sCz;
                int oc = c >> 1;
                float x0 = acc[mi][ni][0], u0 = acc[mi][ni][1];
                float x1 = acc[mi][ni][2], u1 = acc[mi][ni][3];
                C[r * ldc + oc]       = __float2half_rn(x0 / (1.0f + expf(-x0)) * u0);
                C[(r + 8) * ldc + oc] = __float2half_rn(x1 / (1.0f + expf(-x1)) * u1);
                continue;
            }

            // MODE_ROPE
            {
                float2 v0, v1;
                v0.x = acc[mi][ni][0];  v0.y = acc[mi][ni][1];
                v1.x = acc[mi][ni][2];  v1.y = acc[mi][ni][3];
                if (c >= 2048) {
                    int d = c - 2048;
                    int b0 = (int)(r >> 10), s0 = (int)(r & 1023);
                    int b1 = (int)((r + 8) >> 10), s1 = (int)((r + 8) & 1023);
                    aux[((long long)b0 * DIM + d) * SEQ + s0]     = __float2half_rn(v0.x);
                    aux[((long long)b0 * DIM + d + 1) * SEQ + s0] = __float2half_rn(v0.y);
                    aux[((long long)b1 * DIM + d) * SEQ + s1]     = __float2half_rn(v1.x);
                    aux[((long long)b1 * DIM + d + 1) * SEQ + s1] = __float2half_rn(v1.y);
                    continue;
                }
                int jj = (c & 1023) >> 1;
                float freq = exp2f(-13.2877124f * ((float)jj / 512.0f));
                int s0 = (int)(r & 1023), s1 = (int)((r + 8) & 1023);
                float sn, cs;
                sincosf((float)s0 * freq, &sn, &cs);
                float a0 = v0.x * cs - v0.y * sn;
                float b0 = v0.y * cs + v0.x * sn;
                sincosf((float)s1 * freq, &sn, &cs);
                float a1 = v1.x * cs - v1.y * sn;
                float b1 = v1.y * cs + v1.x * sn;
                __half* C = (__half*)Cv;
                *(__half2*)(C + r * (long long)ldc + c) =
                    __floats2half2_rn(a0, b0);
                *(__half2*)(C + (r + 8) * (long long)ldc + c) =
                    __floats2half2_rn(a1, b1);
            }
        }
    }
}

// ---------------------------------------------------------------------------
// Split-K reduce: out(fp16) = p0 + p1 (+ R fp16)
// ---------------------------------------------------------------------------
__global__ void reduce_kernel(const float* __restrict__ part, long long skStride,
                              const __half* __restrict__ R, __half* __restrict__ out)
{
    long long i = ((long long)blockIdx.x * 256 + threadIdx.x) * 4;
    float4 p0 = *(const float4*)(part + i);
    float4 p1 = *(const float4*)(part + skStride + i);
    float vx = p0.x + p1.x, vy = p0.y + p1.y;
    float vz = p0.z + p1.z, vw = p0.w + p1.w;
    if (R) {
        __half2 r0 = *(const __half2*)(R + i);
        __half2 r1 = *(const __half2*)(R + i + 2);
        vx += __half2float(r0.x); vy += __half2float(r0.y);
        vz += __half2float(r1.x); vw += __half2float(r1.y);
    }
    __half2* o = (__half2*)(out + i);
    o[0] = __floats2half2_rn(vx, vy);
    o[1] = __floats2half2_rn(vz, vw);
}

// ---------------------------------------------------------------------------
// Aux kernels
// ---------------------------------------------------------------------------
__global__ void convert_weights_kernel(const float* __restrict__ src,
                                       __half* __restrict__ dst)
{
    long long i = ((long long)blockIdx.x * 256 + threadIdx.x) * 4;
    float4 v = *(const float4*)(src + i);
    __half2* o = (__half2*)(dst + i);
    o[0] = __floats2half2_rn(v.x, v.y);
    o[1] = __floats2half2_rn(v.z, v.w);
}

__global__ void embed_kernel(const int* __restrict__ ids,
                             const float* __restrict__ embed, __half* __restrict__ h)
{
    int bs = blockIdx.x;
    long long tok = ids[bs];
    const float4* src = (const float4*)(embed + tok * DIM);
    float4 v = src[threadIdx.x];
    __half2* o = (__half2*)(h + (long long)bs * DIM + threadIdx.x * 4);
    o[0] = __floats2half2_rn(v.x, v.y);
    o[1] = __floats2half2_rn(v.z, v.w);
}

// softmax over (p0+p1)*scale rows; writes fp16 probs
__global__ void softmax_split_kernel(const float* __restrict__ part, long long skStride,
                                     __half* __restrict__ Sm, float scale)
{
    __shared__ float red[256];
    long long row = blockIdx.x;
    const float* r0 = part + row * SEQ;
    const float* r1 = r0 + skStride;
    int t = threadIdx.x;
    float4 a = ((const float4*)r0)[t];
    float4 b = ((const float4*)r1)[t];
    float4 v;
    v.x = (a.x + b.x) * scale; v.y = (a.y + b.y) * scale;
    v.z = (a.z + b.z) * scale; v.w = (a.w + b.w) * scale;

    float m = fmaxf(fmaxf(v.x, v.y), fmaxf(v.z, v.w));
    red[t] = m; __syncthreads();
    for (int w = 128; w > 0; w >>= 1) { if (t < w) red[t] = fmaxf(red[t], red[t + w]); __syncthreads(); }
    m = red[0]; __syncthreads();
    float e0 = expf(v.x - m), e1 = expf(v.y - m), e2 = expf(v.z - m), e3 = expf(v.w - m);
    red[t] = e0 + e1 + e2 + e3; __syncthreads();
    for (int w = 128; w > 0; w >>= 1) { if (t < w) red[t] += red[t + w]; __syncthreads(); }
    float inv = 1.0f / red[0];
    __half2* o = (__half2*)(Sm + row * SEQ + t * 4);
    o[0] = __floats2half2_rn(e0 * inv, e1 * inv);
    o[1] = __floats2half2_rn(e2 * inv, e3 * inv);
}

// ---------------------------------------------------------------------------
// Host side
// ---------------------------------------------------------------------------
template<int MODE>
static void gemm(const __half* A, int lda, long long sAz,
                 const __half* B, int ldb, long long sBz,
                 void* C, int ldc, long long sCz,
                 int M, int N, int K, float alpha, int bz,
                 int SK = 1, long long sSkz = 0, __half* aux = nullptr)
{
    dim3 grid(N / BN, M / BM, bz * SK);
    h_gemm<MODE><<<grid, 128, GEMM_SMEM>>>(A, lda, sAz, B, ldb, sBz,
                                           C, ldc, sCz, K / SK, alpha,
                                           SK, sSkz, aux);
}

extern "C" void kernel_launch(void* const* d_in, const int* in_sizes, int n_in,
                              void* d_out, int out_size)
{
    (void)in_sizes; (void)n_in; (void)out_size;
    const int*   ids    = (const int*)d_in[0];
    const float* blocks = (const float*)d_in[1];
    float*       out    = (float*)d_out;

    static int attr_done = 0;
    if (!attr_done) {
        cudaFuncSetAttribute(h_gemm<MODE_PLAIN>,
                             cudaFuncAttributeMaxDynamicSharedMemorySize, GEMM_SMEM);
        cudaFuncSetAttribute(h_gemm<MODE_SILU>,
                             cudaFuncAttributeMaxDynamicSharedMemorySize, GEMM_SMEM);
        cudaFuncSetAttribute(h_gemm<MODE_ROPE>,
                             cudaFuncAttributeMaxDynamicSharedMemorySize, GEMM_SMEM);
        attr_done = 1;
    }

    __half *w, *h, *qkv, *vt, *s, *a, *t;
    float *part;
    cudaGetSymbolAddress((void**)&w,    g_w);
    cudaGetSymbolAddress((void**)&h,    g_h);
    cudaGetSymbolAddress((void**)&qkv,  g_qkv);
    cudaGetSymbolAddress((void**)&vt,   g_vt);
    cudaGetSymbolAddress((void**)&s,    g_s);
    cudaGetSymbolAddress((void**)&a,    g_a);
    cudaGetSymbolAddress((void**)&t,    g_t);
    cudaGetSymbolAddress((void**)&part, g_part);

    const long long SD3 = (long long)SEQ * 3072;
    const long long SD  = (long long)SEQ * DIM;
    const long long SS  = (long long)SEQ * SEQ;
    const long long SKS_S = (long long)BATCH * SS;   // scores partial stride
    const long long SKS_D = (long long)MTOK * DIM;   // dim-output partial stride
    const int RED_GRID  = (int)(SKS_D / 4 / 256);

    convert_weights_kernel<<<(int)(NWEIGHT / 4 / 256), 256>>>(blocks + LAYER0_OFF, w);
    embed_kernel<<<MTOK, 256>>>(ids, blocks, h);

    for (int l = 0; l < 2; l++) {
        const __half* Wqkv = w + (long long)l * LAYER_STRIDE;
        const __half* Wo   = Wqkv + 3LL * DIM * DIM;
        const __half* Wgu  = Wo + (long long)DIM * DIM;
        const __half* Wd   = Wgu + 2LL * FFDIM * DIM;

        // qkv: q,k -> qkv (roped); v -> vt (transposed)
        gemm<MODE_ROPE>(h, DIM, 0, Wqkv, DIM, 0, qkv, 3 * DIM, 0,
                        MTOK, 3 * DIM, DIM, 1.0f, 1, 1, 0, vt);
        // scores partial = q @ k^T (split-K=2); softmax fuses reduce+scale
        gemm<MODE_PLAIN>(qkv, 3 * DIM, SD3, qkv + 1024, 3 * DIM, SD3,
                         part, SEQ, SS, SEQ, SEQ, DIM, 1.0f, BATCH, 2, SKS_S);
        softmax_split_kernel<<<BATCH * SEQ, 256>>>(part, SKS_S, s, 1.0f / 32.0f);
        // a = attn @ V (split-K=2 + reduce)
        gemm<MODE_PLAIN>(s, SEQ, SS, vt, SEQ, SD, part, DIM, SD,
                         SEQ, DIM, SEQ, 1.0f, BATCH, 2, SKS_D);
        reduce_kernel<<<RED_GRID, 256>>>(part, SKS_D, nullptr, a);
        // h = a @ Wo^T + h (split-K=2 + reduce w/ residual)
        gemm<MODE_PLAIN>(a, DIM, 0, Wo, DIM, 0, part, DIM, 0,
                         MTOK, DIM, DIM, 1.0f, 1, 2, SKS_D);
        reduce_kernel<<<RED_GRID, 256>>>(part, SKS_D, h, h);
        // t = silu(h@Wg^T) * (h@Wu^T)
        gemm<MODE_SILU>(h, DIM, 0, Wgu, DIM, 0, t, FFDIM, 0,
                        MTOK, 2 * FFDIM, DIM, 1.0f, 1);
        // h = t @ Wd^T + h (split-K=2 + reduce w/ residual)
        gemm<MODE_PLAIN>(t, FFDIM, 0, Wd, FFDIM, 0, part, DIM, 0,
                         MTOK, DIM, FFDIM, 1.0f, 1, 2, SKS_D);
        reduce_kernel<<<RED_GRID, 256>>>(part, SKS_D, h, h);
    }

    gemm<MODE_PLAIN>(h, DIM, 0, w + 2 * LAYER_STRIDE, DIM, 0, out, VOC, 0,
                     MTOK, VOC, DIM, 1.0f, 1);
}

// round 16
// speedup vs baseline: 1.8524x; 1.0075x over previous
#include <cuda_runtime.h>
#include <cuda_fp16.h>
#include <math.h>
#include <stdint.h>

// ---------------------------------------------------------------------------
// Model dims
// ---------------------------------------------------------------------------
#define DIM   1024
#define FFDIM 4096
#define VOC   32000
#define SEQ   1024
#define BATCH 2
#define MTOK  (BATCH * SEQ)

#define LAYER0_OFF   32768000LL
#define LAYER_STRIDE 16777216LL
#define NWEIGHT      (2 * LAYER_STRIDE + (long long)VOC * DIM)

// ---------------------------------------------------------------------------
// Scratch (activations + weights fp16; split-K partials + logits fp32)
// ---------------------------------------------------------------------------
__device__ __half g_w  [NWEIGHT];
__device__ __half g_h  [MTOK * DIM];
__device__ __half g_qkv[MTOK * 3 * DIM];     // q,k pair-interleaved; v unused
__device__ __half g_vt [BATCH * DIM * SEQ];
__device__ __half g_s  [BATCH * SEQ * SEQ];
__device__ __half g_a  [MTOK * DIM];
__device__ __half g_t  [MTOK * FFDIM];
__device__ float  g_part[2LL * BATCH * SEQ * SEQ];  // 2 split-K slices

// ---------------------------------------------------------------------------
// helpers
// ---------------------------------------------------------------------------
__device__ __forceinline__ uint32_t smem_u32(const void* p) {
    uint32_t a;
    asm("{ .reg .u64 t; cvta.to.shared.u64 t, %1; cvt.u32.u64 %0, t; }" : "=r"(a) : "l"(p));
    return a;
}
#define CP_ASYNC16(dst, src) \
    asm volatile("cp.async.cg.shared.global [%0], [%1], 16;" :: "r"(dst), "l"(src))
#define CP_COMMIT() asm volatile("cp.async.commit_group;" ::: "memory")
#define CP_WAIT(n)  asm volatile("cp.async.wait_group %0;" :: "n"(n) : "memory")

#define LDSM4(r0, r1, r2, r3, addr) \
    asm volatile("ldmatrix.sync.aligned.m8n8.x4.shared.b16 {%0,%1,%2,%3}, [%4];" \
        : "=r"(r0), "=r"(r1), "=r"(r2), "=r"(r3) : "r"(addr))

__device__ __forceinline__ void mma16n8k16(float c[4], const uint32_t a[4],
                                           const uint32_t b[2]) {
    asm volatile(
        "mma.sync.aligned.m16n8k16.row.col.f32.f16.f16.f32 "
        "{%0,%1,%2,%3}, {%4,%5,%6,%7}, {%8,%9}, {%0,%1,%2,%3};"
        : "+f"(c[0]), "+f"(c[1]), "+f"(c[2]), "+f"(c[3])
        : "r"(a[0]), "r"(a[1]), "r"(a[2]), "r"(a[3]), "r"(b[0]), "r"(b[1]));
}

// ---------------------------------------------------------------------------
// fp16 GEMM (fp32 accum), cp.async 3-stage, BK=32, ldmatrix loads,
// 128 thr, 4 warps (2Mx2N). BM=128 fixed; BNT in {128, 64}.
//   BNT=128: warp tile 64x64, 3 CTAs/SM  (big GEMMs, all modes)
//   BNT=64 : warp tile 64x32, 4 CTAs/SM  (small N=1024 GEMMs, PLAIN only)
// C[M,N] = alpha*A@B^T. Modes: PLAIN / SILU / ROPE. Optional split-K=2.
// ---------------------------------------------------------------------------
#define MODE_PLAIN 0
#define MODE_SILU  2
#define MODE_ROPE  3

#define BM 128
#define BK 32
#define RSH 40                         // halves per smem row (80 B)
#define STAGES 3
#define SMEM_OF(BNT) (STAGES * (128 + (BNT)) * RSH * 2)

template<int MODE, int BNT>
__global__ __launch_bounds__(128, (BNT == 64 ? 4 : 3))
void h_gemm(const __half* __restrict__ A, int lda, long long sAz,
            const __half* __restrict__ B, int ldb, long long sBz,
            void* __restrict__ Cv, int ldc, long long sCz,
            int K, float alpha, int SK, long long sSkz,
            __half* __restrict__ aux)
{
    constexpr int WNI   = BNT / 16;            // n-fragments per warp
    constexpr int STG_H = (128 + BNT) * RSH;   // halves per stage
    constexpr int B_H   = 128 * RSH;           // B offset in stage (halves)
    constexpr int NCH   = (128 + BNT) * 4;     // 16B chunks per stage

    extern __shared__ __half smh[];
    const uint32_t smb = smem_u32(smh);

    const int tid  = threadIdx.x;
    const int warp = tid >> 5, lane = tid & 31;
    const int wm = warp & 1;
    const int wn = warp >> 1;
    const int g  = lane >> 2;
    const int tg = lane & 3;

    int bzr = blockIdx.z;
    int sk = 0;
    if (SK > 1) { sk = bzr & 1; bzr >>= 1; }
    const long long bz = bzr;
    A += bz * sAz + (long long)sk * K;
    B += bz * sBz + (long long)sk * K;
    const int row0 = blockIdx.y * BM;
    const int col0 = blockIdx.x * BNT;

    // ldmatrix per-lane base offsets (halves within stage)
    uint32_t aoff[4], boff[WNI / 2];
#pragma unroll
    for (int mi = 0; mi < 4; mi++) {
        int r = wm * 64 + mi * 16 + ((lane >> 3) & 1) * 8 + (lane & 7);
        aoff[mi] = r * RSH + (lane >> 4) * 8;
    }
#pragma unroll
    for (int p = 0; p < WNI / 2; p++) {
        int c = wn * (BNT / 2) + p * 16 + ((lane >> 4) & 1) * 8 + (lane & 7);
        boff[p] = c * RSH + ((lane >> 3) & 1) * 8;
    }

    auto fill = [&](int st, int k0) {
        uint32_t base = smb + st * (STG_H * 2);
#pragma unroll
        for (int j = 0; j < NCH / 128; j++) {
            int id = tid + 128 * j;           // 0..NCH-1
            int isB = id >= 512;              // A = 128 rows * 4 chunks
            int r  = (isB ? id - 512 : id) >> 2;
            int kc = id & 3;                  // 16B chunk (8 halves)
            long long srow;
            if (isB) {
                int n = col0 + r;
                if (MODE == MODE_SILU) {
                    srow = (n >> 1) + (n & 1) * FFDIM;
                } else if (MODE == MODE_ROPE) {
                    if (n < 2048) {
                        int m = n & 1023;
                        srow = (n & 1024) + (m >> 1) + (m & 1) * 512;
                    } else srow = n;
                } else srow = n;
            } else srow = row0 + r;
            const __half* src = (isB ? B + srow * ldb : A + srow * lda) + k0 + kc * 8;
            uint32_t dst = base + (isB ? B_H * 2 : 0) + r * (RSH * 2) + kc * 16;
            CP_ASYNC16(dst, src);
        }
    };

    float acc[4][WNI][4];
#pragma unroll
    for (int mi = 0; mi < 4; mi++)
#pragma unroll
        for (int ni = 0; ni < WNI; ni++)
#pragma unroll
            for (int j = 0; j < 4; j++) acc[mi][ni][j] = 0.0f;

    const int NK = K / BK;
    fill(0, 0);       CP_COMMIT();
    fill(1, BK);      CP_COMMIT();

    int st = 0;
    for (int it = 0; it < NK; it++) {
        CP_WAIT(1);
        __syncthreads();

        const uint32_t stbase = smb + st * (STG_H * 2);
#pragma unroll
        for (int kk = 0; kk < BK; kk += 16) {
            uint32_t af[4][4], bf[WNI][2];
#pragma unroll
            for (int mi = 0; mi < 4; mi++)
                LDSM4(af[mi][0], af[mi][1], af[mi][2], af[mi][3],
                      stbase + (aoff[mi] + kk) * 2);
#pragma unroll
            for (int p = 0; p < WNI / 2; p++)
                LDSM4(bf[2 * p][0], bf[2 * p][1], bf[2 * p + 1][0], bf[2 * p + 1][1],
                      stbase + B_H * 2 + (boff[p] + kk) * 2);
#pragma unroll
            for (int mi = 0; mi < 4; mi++)
#pragma unroll
                for (int ni = 0; ni < WNI; ni++)
                    mma16n8k16(acc[mi][ni], af[mi], bf[ni]);
        }

        int nf = it + 2;
        if (nf < NK) {
            int fst = st + 2; if (fst >= STAGES) fst -= STAGES;
            fill(fst, nf * BK);
        }
        CP_COMMIT();
        if (++st == STAGES) st = 0;
    }

    // ---- epilogue ----
#pragma unroll
    for (int mi = 0; mi < 4; mi++) {
        long long r = row0 + wm * 64 + mi * 16 + g;
#pragma unroll
        for (int ni = 0; ni < WNI; ni++) {
            int c = col0 + wn * (BNT / 2) + ni * 8 + tg * 2;

            if (MODE == MODE_PLAIN) {
                float* C = (float*)Cv + bz * sCz + (long long)sk * sSkz;
                float2 v0, v1;
                v0.x = acc[mi][ni][0] * alpha;  v0.y = acc[mi][ni][1] * alpha;
                v1.x = acc[mi][ni][2] * alpha;  v1.y = acc[mi][ni][3] * alpha;
                *(float2*)(C + r * (long long)ldc + c)       = v0;
                *(float2*)(C + (r + 8) * (long long)ldc + c) = v1;
                continue;
            }

            if (MODE == MODE_SILU) {
                __half* C = (__half*)Cv + bz * sCz;
                int oc = c >> 1;
                float x0 = acc[mi][ni][0], u0 = acc[mi][ni][1];
                float x1 = acc[mi][ni][2], u1 = acc[mi][ni][3];
                C[r * ldc + oc]       = __float2half_rn(x0 / (1.0f + expf(-x0)) * u0);
                C[(r + 8) * ldc + oc] = __float2half_rn(x1 / (1.0f + expf(-x1)) * u1);
                continue;
            }

            // MODE_ROPE
            {
                float2 v0, v1;
                v0.x = acc[mi][ni][0];  v0.y = acc[mi][ni][1];
                v1.x = acc[mi][ni][2];  v1.y = acc[mi][ni][3];
                if (c >= 2048) {
                    int d = c - 2048;
                    int b0 = (int)(r >> 10), s0 = (int)(r & 1023);
                    int b1 = (int)((r + 8) >> 10), s1 = (int)((r + 8) & 1023);
                    aux[((long long)b0 * DIM + d) * SEQ + s0]     = __float2half_rn(v0.x);
                    aux[((long long)b0 * DIM + d + 1) * SEQ + s0] = __float2half_rn(v0.y);
                    aux[((long long)b1 * DIM + d) * SEQ + s1]     = __float2half_rn(v1.x);
                    aux[((long long)b1 * DIM + d + 1) * SEQ + s1] = __float2half_rn(v1.y);
                    continue;
                }
                int jj = (c & 1023) >> 1;
                float freq = exp2f(-13.2877124f * ((float)jj / 512.0f));
                int s0 = (int)(r & 1023), s1 = (int)((r + 8) & 1023);
                float sn, cs;
                sincosf((float)s0 * freq, &sn, &cs);
                float a0 = v0.x * cs - v0.y * sn;
                float b0 = v0.y * cs + v0.x * sn;
                sincosf((float)s1 * freq, &sn, &cs);
                float a1 = v1.x * cs - v1.y * sn;
                float b1 = v1.y * cs + v1.x * sn;
                __half* C = (__half*)Cv;
                *(__half2*)(C + r * (long long)ldc + c) =
                    __floats2half2_rn(a0, b0);
                *(__half2*)(C + (r + 8) * (long long)ldc + c) =
                    __floats2half2_rn(a1, b1);
            }
        }
    }
}

// ---------------------------------------------------------------------------
// Split-K reduce: out(fp16) = p0 + p1 (+ R fp16)
// ---------------------------------------------------------------------------
__global__ void reduce_kernel(const float* __restrict__ part, long long skStride,
                              const __half* __restrict__ R, __half* __restrict__ out)
{
    long long i = ((long long)blockIdx.x * 256 + threadIdx.x) * 4;
    float4 p0 = *(const float4*)(part + i);
    float4 p1 = *(const float4*)(part + skStride + i);
    float vx = p0.x + p1.x, vy = p0.y + p1.y;
    float vz = p0.z + p1.z, vw = p0.w + p1.w;
    if (R) {
        __half2 r0 = *(const __half2*)(R + i);
        __half2 r1 = *(const __half2*)(R + i + 2);
        vx += __half2float(r0.x); vy += __half2float(r0.y);
        vz += __half2float(r1.x); vw += __half2float(r1.y);
    }
    __half2* o = (__half2*)(out + i);
    o[0] = __floats2half2_rn(vx, vy);
    o[1] = __floats2half2_rn(vz, vw);
}

// ---------------------------------------------------------------------------
// Aux kernels
// ---------------------------------------------------------------------------
__global__ void convert_weights_kernel(const float* __restrict__ src,
                                       __half* __restrict__ dst)
{
    long long i = ((long long)blockIdx.x * 256 + threadIdx.x) * 4;
    float4 v = *(const float4*)(src + i);
    __half2* o = (__half2*)(dst + i);
    o[0] = __floats2half2_rn(v.x, v.y);
    o[1] = __floats2half2_rn(v.z, v.w);
}

__global__ void embed_kernel(const int* __restrict__ ids,
                             const float* __restrict__ embed, __half* __restrict__ h)
{
    int bs = blockIdx.x;
    long long tok = ids[bs];
    const float4* src = (const float4*)(embed + tok * DIM);
    float4 v = src[threadIdx.x];
    __half2* o = (__half2*)(h + (long long)bs * DIM + threadIdx.x * 4);
    o[0] = __floats2half2_rn(v.x, v.y);
    o[1] = __floats2half2_rn(v.z, v.w);
}

// softmax over (p0+p1)*scale rows; writes fp16 probs
__global__ void softmax_split_kernel(const float* __restrict__ part, long long skStride,
                                     __half* __restrict__ Sm, float scale)
{
    __shared__ float red[256];
    long long row = blockIdx.x;
    const float* r0 = part + row * SEQ;
    const float* r1 = r0 + skStride;
    int t = threadIdx.x;
    float4 a = ((const float4*)r0)[t];
    float4 b = ((const float4*)r1)[t];
    float4 v;
    v.x = (a.x + b.x) * scale; v.y = (a.y + b.y) * scale;
    v.z = (a.z + b.z) * scale; v.w = (a.w + b.w) * scale;

    float m = fmaxf(fmaxf(v.x, v.y), fmaxf(v.z, v.w));
    red[t] = m; __syncthreads();
    for (int w = 128; w > 0; w >>= 1) { if (t < w) red[t] = fmaxf(red[t], red[t + w]); __syncthreads(); }
    m = red[0]; __syncthreads();
    float e0 = expf(v.x - m), e1 = expf(v.y - m), e2 = expf(v.z - m), e3 = expf(v.w - m);
    red[t] = e0 + e1 + e2 + e3; __syncthreads();
    for (int w = 128; w > 0; w >>= 1) { if (t < w) red[t] += red[t + w]; __syncthreads(); }
    float inv = 1.0f / red[0];
    __half2* o = (__half2*)(Sm + row * SEQ + t * 4);
    o[0] = __floats2half2_rn(e0 * inv, e1 * inv);
    o[1] = __floats2half2_rn(e2 * inv, e3 * inv);
}

// ---------------------------------------------------------------------------
// Host side
// ---------------------------------------------------------------------------
template<int MODE, int BNT>
static void gemm(const __half* A, int lda, long long sAz,
                 const __half* B, int ldb, long long sBz,
                 void* C, int ldc, long long sCz,
                 int M, int N, int K, float alpha, int bz,
                 int SK = 1, long long sSkz = 0, __half* aux = nullptr)
{
    dim3 grid(N / BNT, M / BM, bz * SK);
    h_gemm<MODE, BNT><<<grid, 128, SMEM_OF(BNT)>>>(A, lda, sAz, B, ldb, sBz,
                                                   C, ldc, sCz, K / SK, alpha,
                                                   SK, sSkz, aux);
}

extern "C" void kernel_launch(void* const* d_in, const int* in_sizes, int n_in,
                              void* d_out, int out_size)
{
    (void)in_sizes; (void)n_in; (void)out_size;
    const int*   ids    = (const int*)d_in[0];
    const float* blocks = (const float*)d_in[1];
    float*       out    = (float*)d_out;

    static int attr_done = 0;
    if (!attr_done) {
        cudaFuncSetAttribute(h_gemm<MODE_PLAIN, 128>,
                             cudaFuncAttributeMaxDynamicSharedMemorySize, SMEM_OF(128));
        cudaFuncSetAttribute(h_gemm<MODE_SILU, 128>,
                             cudaFuncAttributeMaxDynamicSharedMemorySize, SMEM_OF(128));
        cudaFuncSetAttribute(h_gemm<MODE_ROPE, 128>,
                             cudaFuncAttributeMaxDynamicSharedMemorySize, SMEM_OF(128));
        cudaFuncSetAttribute(h_gemm<MODE_PLAIN, 64>,
                             cudaFuncAttributeMaxDynamicSharedMemorySize, SMEM_OF(64));
        attr_done = 1;
    }

    __half *w, *h, *qkv, *vt, *s, *a, *t;
    float *part;
    cudaGetSymbolAddress((void**)&w,    g_w);
    cudaGetSymbolAddress((void**)&h,    g_h);
    cudaGetSymbolAddress((void**)&qkv,  g_qkv);
    cudaGetSymbolAddress((void**)&vt,   g_vt);
    cudaGetSymbolAddress((void**)&s,    g_s);
    cudaGetSymbolAddress((void**)&a,    g_a);
    cudaGetSymbolAddress((void**)&t,    g_t);
    cudaGetSymbolAddress((void**)&part, g_part);

    const long long SD3 = (long long)SEQ * 3072;
    const long long SD  = (long long)SEQ * DIM;
    const long long SS  = (long long)SEQ * SEQ;
    const long long SKS_S = (long long)BATCH * SS;   // scores partial stride
    const long long SKS_D = (long long)MTOK * DIM;   // dim-output partial stride
    const int RED_GRID  = (int)(SKS_D / 4 / 256);

    convert_weights_kernel<<<(int)(NWEIGHT / 4 / 256), 256>>>(blocks + LAYER0_OFF, w);
    embed_kernel<<<MTOK, 256>>>(ids, blocks, h);

    for (int l = 0; l < 2; l++) {
        const __half* Wqkv = w + (long long)l * LAYER_STRIDE;
        const __half* Wo   = Wqkv + 3LL * DIM * DIM;
        const __half* Wgu  = Wo + (long long)DIM * DIM;
        const __half* Wd   = Wgu + 2LL * FFDIM * DIM;

        // qkv: q,k -> qkv (roped); v -> vt (transposed)
        gemm<MODE_ROPE, 128>(h, DIM, 0, Wqkv, DIM, 0, qkv, 3 * DIM, 0,
                             MTOK, 3 * DIM, DIM, 1.0f, 1, 1, 0, vt);
        // scores partial = q @ k^T (split-K=2, BN=64); softmax reduces+scales
        gemm<MODE_PLAIN, 64>(qkv, 3 * DIM, SD3, qkv + 1024, 3 * DIM, SD3,
                             part, SEQ, SS, SEQ, SEQ, DIM, 1.0f, BATCH, 2, SKS_S);
        softmax_split_kernel<<<BATCH * SEQ, 256>>>(part, SKS_S, s, 1.0f / 32.0f);
        // a = attn @ V (split-K=2, BN=64 + reduce)
        gemm<MODE_PLAIN, 64>(s, SEQ, SS, vt, SEQ, SD, part, DIM, SD,
                             SEQ, DIM, SEQ, 1.0f, BATCH, 2, SKS_D);
        reduce_kernel<<<RED_GRID, 256>>>(part, SKS_D, nullptr, a);
        // h = a @ Wo^T + h (split-K=2, BN=64 + reduce w/ residual)
        gemm<MODE_PLAIN, 64>(a, DIM, 0, Wo, DIM, 0, part, DIM, 0,
                             MTOK, DIM, DIM, 1.0f, 1, 2, SKS_D);
        reduce_kernel<<<RED_GRID, 256>>>(part, SKS_D, h, h);
        // t = silu(h@Wg^T) * (h@Wu^T)
        gemm<MODE_SILU, 128>(h, DIM, 0, Wgu, DIM, 0, t, FFDIM, 0,
                             MTOK, 2 * FFDIM, DIM, 1.0f, 1);
        // h = t @ Wd^T + h (split-K=2, BN=64 + reduce w/ residual)
        gemm<MODE_PLAIN, 64>(t, FFDIM, 0, Wd, FFDIM, 0, part, DIM, 0,
                             MTOK, DIM, FFDIM, 1.0f, 1, 2, SKS_D);
        reduce_kernel<<<RED_GRID, 256>>>(part, SKS_D, h, h);
    }

    gemm<MODE_PLAIN, 128>(h, DIM, 0, w + 2 * LAYER_STRIDE, DIM, 0, out, VOC, 0,
                          MTOK, VOC, DIM, 1.0f, 1);
}

// round 17
// speedup vs baseline: 2.0566x; 1.1102x over previous
#include <cuda_runtime.h>
#include <cuda_fp16.h>
#include <math.h>
#include <stdint.h>

// ---------------------------------------------------------------------------
// Model dims
// ---------------------------------------------------------------------------
#define DIM   1024
#define FFDIM 4096
#define VOC   32000
#define SEQ   1024
#define BATCH 2
#define MTOK  (BATCH * SEQ)

#define LAYER0_OFF   32768000LL
#define LAYER_STRIDE 16777216LL
#define NWEIGHT      (2 * LAYER_STRIDE + (long long)VOC * DIM)

// ---------------------------------------------------------------------------
// Scratch (activations + weights fp16; split-K partials + logits fp32)
// ---------------------------------------------------------------------------
__device__ __half g_w  [NWEIGHT];
__device__ __half g_h  [MTOK * DIM];
__device__ __half g_qkv[MTOK * 3 * DIM];     // q,k pair-interleaved; v unused
__device__ __half g_vt [BATCH * DIM * SEQ];
__device__ __half g_s  [BATCH * SEQ * SEQ];
__device__ __half g_a  [MTOK * DIM];
__device__ __half g_t  [MTOK * FFDIM];
__device__ float  g_part[2LL * BATCH * SEQ * SEQ];  // 2 split-K slices

// ---------------------------------------------------------------------------
// helpers
// ---------------------------------------------------------------------------
__device__ __forceinline__ uint32_t smem_u32(const void* p) {
    uint32_t a;
    asm("{ .reg .u64 t; cvta.to.shared.u64 t, %1; cvt.u32.u64 %0, t; }" : "=r"(a) : "l"(p));
    return a;
}
#define CP_ASYNC16(dst, src) \
    asm volatile("cp.async.cg.shared.global [%0], [%1], 16;" :: "r"(dst), "l"(src))
#define CP_COMMIT() asm volatile("cp.async.commit_group;" ::: "memory")
#define CP_WAIT(n)  asm volatile("cp.async.wait_group %0;" :: "n"(n) : "memory")

#define LDSM4(r0, r1, r2, r3, addr) \
    asm volatile("ldmatrix.sync.aligned.m8n8.x4.shared.b16 {%0,%1,%2,%3}, [%4];" \
        : "=r"(r0), "=r"(r1), "=r"(r2), "=r"(r3) : "r"(addr))

__device__ __forceinline__ void mma16n8k16(float c[4], const uint32_t a[4],
                                           const uint32_t b[2]) {
    asm volatile(
        "mma.sync.aligned.m16n8k16.row.col.f32.f16.f16.f32 "
        "{%0,%1,%2,%3}, {%4,%5,%6,%7}, {%8,%9}, {%0,%1,%2,%3};"
        : "+f"(c[0]), "+f"(c[1]), "+f"(c[2]), "+f"(c[3])
        : "r"(a[0]), "r"(a[1]), "r"(a[2]), "r"(a[3]), "r"(b[0]), "r"(b[1]));
}

// ---------------------------------------------------------------------------
// fp16 GEMM (fp32 accum), cp.async 2-stage double buffer, BK=64,
// SW128-swizzled 128B smem rows (no padding), ldmatrix loads.
// 128 thr, 4 warps (2Mx2N). BM=128; BNT in {128 (3 CTAs/SM), 64 (4 CTAs/SM)}.
// C[M,N] = alpha*A@B^T. Modes: PLAIN / SILU / ROPE. Optional split-K=2.
// ---------------------------------------------------------------------------
#define MODE_PLAIN 0
#define MODE_SILU  2
#define MODE_ROPE  3

#define BM 128
#define BK 64
#define STAGES 2
// stage: (128 + BNT) rows * 128 bytes
#define SMEM_OF(BNT) (STAGES * (128 + (BNT)) * 128)

template<int MODE, int BNT>
__global__ __launch_bounds__(128, (BNT == 64 ? 4 : 3))
void h_gemm(const __half* __restrict__ A, int lda, long long sAz,
            const __half* __restrict__ B, int ldb, long long sBz,
            void* __restrict__ Cv, int ldc, long long sCz,
            int K, float alpha, int SK, long long sSkz,
            __half* __restrict__ aux)
{
    constexpr int WNI    = BNT / 16;             // n-fragments per warp
    constexpr int STG_B  = (128 + BNT) * 128;    // bytes per stage
    constexpr int BOFF_B = 128 * 128;            // B offset in stage (bytes)
    constexpr int NCH    = (128 + BNT) * 8;      // 16B chunks per stage

    extern __shared__ __half smh[];
    const uint32_t smb = smem_u32(smh);

    const int tid  = threadIdx.x;
    const int warp = tid >> 5, lane = tid & 31;
    const int wm = warp & 1;
    const int wn = warp >> 1;
    const int g  = lane >> 2;
    const int tg = lane & 3;

    int bzr = blockIdx.z;
    int sk = 0;
    if (SK > 1) { sk = bzr & 1; bzr >>= 1; }
    const long long bz = bzr;
    A += bz * sAz + (long long)sk * K;
    B += bz * sBz + (long long)sk * K;
    const int row0 = blockIdx.y * BM;
    const int col0 = blockIdx.x * BNT;

    // ldmatrix per-lane bases: row byte offset + per-row XOR for SW128
    uint32_t abase[4], axor[4], bbase[WNI / 2], bxor[WNI / 2];
    const int lsel = (lane >> 4);          // chunk-select half of the x4 load
#pragma unroll
    for (int mi = 0; mi < 4; mi++) {
        int r = wm * 64 + mi * 16 + ((lane >> 3) & 1) * 8 + (lane & 7);
        abase[mi] = r * 128;
        axor[mi]  = (r & 7) << 4;
    }
#pragma unroll
    for (int p = 0; p < WNI / 2; p++) {
        int c = wn * (BNT / 2) + p * 16 + ((lane >> 4) & 1) * 8 + (lane & 7);
        bbase[p] = c * 128;
        bxor[p]  = (c & 7) << 4;
    }
    const int bsel = (lane >> 3) & 1;

    auto fill = [&](int st, int k0) {
        uint32_t base = smb + st * STG_B;
#pragma unroll
        for (int j = 0; j < NCH / 128; j++) {
            int id = tid + 128 * j;           // 0..NCH-1
            int isB = id >= 1024;             // A = 128 rows * 8 chunks
            int r  = (isB ? id - 1024 : id) >> 3;
            int kc = id & 7;                  // 16B chunk within 128B row
            long long srow;
            if (isB) {
                int n = col0 + r;
                if (MODE == MODE_SILU) {
                    srow = (n >> 1) + (n & 1) * FFDIM;
                } else if (MODE == MODE_ROPE) {
                    if (n < 2048) {
                        int m = n & 1023;
                        srow = (n & 1024) + (m >> 1) + (m & 1) * 512;
                    } else srow = n;
                } else srow = n;
            } else srow = row0 + r;
            const __half* src = (isB ? B + srow * ldb : A + srow * lda) + k0 + kc * 8;
            uint32_t dst = base + (isB ? BOFF_B : 0) + r * 128
                         + ((kc ^ (r & 7)) << 4);
            CP_ASYNC16(dst, src);
        }
    };

    float acc[4][WNI][4];
#pragma unroll
    for (int mi = 0; mi < 4; mi++)
#pragma unroll
        for (int ni = 0; ni < WNI; ni++)
#pragma unroll
            for (int j = 0; j < 4; j++) acc[mi][ni][j] = 0.0f;

    const int NK = K / BK;
    fill(0, 0);
    CP_COMMIT();

    for (int it = 0; it < NK; it++) {
        CP_WAIT(0);
        __syncthreads();

        // fill other buffer (freed by the barrier) while computing this one
        if (it + 1 < NK) fill((it + 1) & 1, (it + 1) * BK);
        CP_COMMIT();

        const uint32_t stbase = smb + (it & 1) * STG_B;
#pragma unroll
        for (int kk = 0; kk < BK; kk += 16) {
            uint32_t af[4][4], bf[WNI][2];
            uint32_t acn = (((kk >> 3) + lsel) << 4);
            uint32_t bcn = (((kk >> 3) + bsel) << 4);
#pragma unroll
            for (int mi = 0; mi < 4; mi++)
                LDSM4(af[mi][0], af[mi][1], af[mi][2], af[mi][3],
                      stbase + abase[mi] + (acn ^ axor[mi]));
#pragma unroll
            for (int p = 0; p < WNI / 2; p++)
                LDSM4(bf[2 * p][0], bf[2 * p][1], bf[2 * p + 1][0], bf[2 * p + 1][1],
                      stbase + BOFF_B + bbase[p] + (bcn ^ bxor[p]));
#pragma unroll
            for (int mi = 0; mi < 4; mi++)
#pragma unroll
                for (int ni = 0; ni < WNI; ni++)
                    mma16n8k16(acc[mi][ni], af[mi], bf[ni]);
        }
    }

    // ---- epilogue ----
#pragma unroll
    for (int mi = 0; mi < 4; mi++) {
        long long r = row0 + wm * 64 + mi * 16 + g;
#pragma unroll
        for (int ni = 0; ni < WNI; ni++) {
            int c = col0 + wn * (BNT / 2) + ni * 8 + tg * 2;

            if (MODE == MODE_PLAIN) {
                float* C = (float*)Cv + bz * sCz + (long long)sk * sSkz;
                float2 v0, v1;
                v0.x = acc[mi][ni][0] * alpha;  v0.y = acc[mi][ni][1] * alpha;
                v1.x = acc[mi][ni][2] * alpha;  v1.y = acc[mi][ni][3] * alpha;
                *(float2*)(C + r * (long long)ldc + c)       = v0;
                *(float2*)(C + (r + 8) * (long long)ldc + c) = v1;
                continue;
            }

            if (MODE == MODE_SILU) {
                __half* C = (__half*)Cv + bz * sCz;
                int oc = c >> 1;
                float x0 = acc[mi][ni][0], u0 = acc[mi][ni][1];
                float x1 = acc[mi][ni][2], u1 = acc[mi][ni][3];
                C[r * ldc + oc]       = __float2half_rn(x0 / (1.0f + expf(-x0)) * u0);
                C[(r + 8) * ldc + oc] = __float2half_rn(x1 / (1.0f + expf(-x1)) * u1);
                continue;
            }

            // MODE_ROPE
            {
                float2 v0, v1;
                v0.x = acc[mi][ni][0];  v0.y = acc[mi][ni][1];
                v1.x = acc[mi][ni][2];  v1.y = acc[mi][ni][3];
                if (c >= 2048) {
                    int d = c - 2048;
                    int b0 = (int)(r >> 10), s0 = (int)(r & 1023);
                    int b1 = (int)((r + 8) >> 10), s1 = (int)((r + 8) & 1023);
                    aux[((long long)b0 * DIM + d) * SEQ + s0]     = __float2half_rn(v0.x);
                    aux[((long long)b0 * DIM + d + 1) * SEQ + s0] = __float2half_rn(v0.y);
                    aux[((long long)b1 * DIM + d) * SEQ + s1]     = __float2half_rn(v1.x);
                    aux[((long long)b1 * DIM + d + 1) * SEQ + s1] = __float2half_rn(v1.y);
                    continue;
                }
                int jj = (c & 1023) >> 1;
                float freq = exp2f(-13.2877124f * ((float)jj / 512.0f));
                int s0 = (int)(r & 1023), s1 = (int)((r + 8) & 1023);
                float sn, cs;
                sincosf((float)s0 * freq, &sn, &cs);
                float a0 = v0.x * cs - v0.y * sn;
                float b0 = v0.y * cs + v0.x * sn;
                sincosf((float)s1 * freq, &sn, &cs);
                float a1 = v1.x * cs - v1.y * sn;
                float b1 = v1.y * cs + v1.x * sn;
                __half* C = (__half*)Cv;
                *(__half2*)(C + r * (long long)ldc + c) =
                    __floats2half2_rn(a0, b0);
                *(__half2*)(C + (r + 8) * (long long)ldc + c) =
                    __floats2half2_rn(a1, b1);
            }
        }
    }
}

// ---------------------------------------------------------------------------
// Split-K reduce: out(fp16) = p0 + p1 (+ R fp16)
// ---------------------------------------------------------------------------
__global__ void reduce_kernel(const float* __restrict__ part, long long skStride,
                              const __half* __restrict__ R, __half* __restrict__ out)
{
    long long i = ((long long)blockIdx.x * 256 + threadIdx.x) * 4;
    float4 p0 = *(const float4*)(part + i);
    float4 p1 = *(const float4*)(part + skStride + i);
    float vx = p0.x + p1.x, vy = p0.y + p1.y;
    float vz = p0.z + p1.z, vw = p0.w + p1.w;
    if (R) {
        __half2 r0 = *(const __half2*)(R + i);
        __half2 r1 = *(const __half2*)(R + i + 2);
        vx += __half2float(r0.x); vy += __half2float(r0.y);
        vz += __half2float(r1.x); vw += __half2float(r1.y);
    }
    __half2* o = (__half2*)(out + i);
    o[0] = __floats2half2_rn(vx, vy);
    o[1] = __floats2half2_rn(vz, vw);
}

// ---------------------------------------------------------------------------
// Aux kernels
// ---------------------------------------------------------------------------
__global__ void convert_weights_kernel(const float* __restrict__ src,
                                       __half* __restrict__ dst)
{
    long long i = ((long long)blockIdx.x * 256 + threadIdx.x) * 4;
    float4 v = *(const float4*)(src + i);
    __half2* o = (__half2*)(dst + i);
    o[0] = __floats2half2_rn(v.x, v.y);
    o[1] = __floats2half2_rn(v.z, v.w);
}

__global__ void embed_kernel(const int* __restrict__ ids,
                             const float* __restrict__ embed, __half* __restrict__ h)
{
    int bs = blockIdx.x;
    long long tok = ids[bs];
    const float4* src = (const float4*)(embed + tok * DIM);
    float4 v = src[threadIdx.x];
    __half2* o = (__half2*)(h + (long long)bs * DIM + threadIdx.x * 4);
    o[0] = __floats2half2_rn(v.x, v.y);
    o[1] = __floats2half2_rn(v.z, v.w);
}

// softmax over (p0+p1)*scale rows; writes fp16 probs
__global__ void softmax_split_kernel(const float* __restrict__ part, long long skStride,
                                     __half* __restrict__ Sm, float scale)
{
    __shared__ float red[256];
    long long row = blockIdx.x;
    const float* r0 = part + row * SEQ;
    const float* r1 = r0 + skStride;
    int t = threadIdx.x;
    float4 a = ((const float4*)r0)[t];
    float4 b = ((const float4*)r1)[t];
    float4 v;
    v.x = (a.x + b.x) * scale; v.y = (a.y + b.y) * scale;
    v.z = (a.z + b.z) * scale; v.w = (a.w + b.w) * scale;

    float m = fmaxf(fmaxf(v.x, v.y), fmaxf(v.z, v.w));
    red[t] = m; __syncthreads();
    for (int w = 128; w > 0; w >>= 1) { if (t < w) red[t] = fmaxf(red[t], red[t + w]); __syncthreads(); }
    m = red[0]; __syncthreads();
    float e0 = expf(v.x - m), e1 = expf(v.y - m), e2 = expf(v.z - m), e3 = expf(v.w - m);
    red[t] = e0 + e1 + e2 + e3; __syncthreads();
    for (int w = 128; w > 0; w >>= 1) { if (t < w) red[t] += red[t + w]; __syncthreads(); }
    float inv = 1.0f / red[0];
    __half2* o = (__half2*)(Sm + row * SEQ + t * 4);
    o[0] = __floats2half2_rn(e0 * inv, e1 * inv);
    o[1] = __floats2half2_rn(e2 * inv, e3 * inv);
}

// ---------------------------------------------------------------------------
// Host side
// ---------------------------------------------------------------------------
template<int MODE, int BNT>
static void gemm(const __half* A, int lda, long long sAz,
                 const __half* B, int ldb, long long sBz,
                 void* C, int ldc, long long sCz,
                 int M, int N, int K, float alpha, int bz,
                 int SK = 1, long long sSkz = 0, __half* aux = nullptr)
{
    dim3 grid(N / BNT, M / BM, bz * SK);
    h_gemm<MODE, BNT><<<grid, 128, SMEM_OF(BNT)>>>(A, lda, sAz, B, ldb, sBz,
                                                   C, ldc, sCz, K / SK, alpha,
                                                   SK, sSkz, aux);
}

extern "C" void kernel_launch(void* const* d_in, const int* in_sizes, int n_in,
                              void* d_out, int out_size)
{
    (void)in_sizes; (void)n_in; (void)out_size;
    const int*   ids    = (const int*)d_in[0];
    const float* blocks = (const float*)d_in[1];
    float*       out    = (float*)d_out;

    static int attr_done = 0;
    if (!attr_done) {
        cudaFuncSetAttribute(h_gemm<MODE_PLAIN, 128>,
                             cudaFuncAttributeMaxDynamicSharedMemorySize, SMEM_OF(128));
        cudaFuncSetAttribute(h_gemm<MODE_SILU, 128>,
                             cudaFuncAttributeMaxDynamicSharedMemorySize, SMEM_OF(128));
        cudaFuncSetAttribute(h_gemm<MODE_ROPE, 128>,
                             cudaFuncAttributeMaxDynamicSharedMemorySize, SMEM_OF(128));
        cudaFuncSetAttribute(h_gemm<MODE_PLAIN, 64>,
                             cudaFuncAttributeMaxDynamicSharedMemorySize, SMEM_OF(64));
        attr_done = 1;
    }

    __half *w, *h, *qkv, *vt, *s, *a, *t;
    float *part;
    cudaGetSymbolAddress((void**)&w,    g_w);
    cudaGetSymbolAddress((void**)&h,    g_h);
    cudaGetSymbolAddress((void**)&qkv,  g_qkv);
    cudaGetSymbolAddress((void**)&vt,   g_vt);
    cudaGetSymbolAddress((void**)&s,    g_s);
    cudaGetSymbolAddress((void**)&a,    g_a);
    cudaGetSymbolAddress((void**)&t,    g_t);
    cudaGetSymbolAddress((void**)&part, g_part);

    const long long SD3 = (long long)SEQ * 3072;
    const long long SD  = (long long)SEQ * DIM;
    const long long SS  = (long long)SEQ * SEQ;
    const long long SKS_S = (long long)BATCH * SS;   // scores partial stride
    const long long SKS_D = (long long)MTOK * DIM;   // dim-output partial stride
    const int RED_GRID  = (int)(SKS_D / 4 / 256);

    convert_weights_kernel<<<(int)(NWEIGHT / 4 / 256), 256>>>(blocks + LAYER0_OFF, w);
    embed_kernel<<<MTOK, 256>>>(ids, blocks, h);

    for (int l = 0; l < 2; l++) {
        const __half* Wqkv = w + (long long)l * LAYER_STRIDE;
        const __half* Wo   = Wqkv + 3LL * DIM * DIM;
        const __half* Wgu  = Wo + (long long)DIM * DIM;
        const __half* Wd   = Wgu + 2LL * FFDIM * DIM;

        // qkv: q,k -> qkv (roped); v -> vt (transposed)
        gemm<MODE_ROPE, 128>(h, DIM, 0, Wqkv, DIM, 0, qkv, 3 * DIM, 0,
                             MTOK, 3 * DIM, DIM, 1.0f, 1, 1, 0, vt);
        // scores partial = q @ k^T (split-K=2, BN=64); softmax reduces+scales
        gemm<MODE_PLAIN, 64>(qkv, 3 * DIM, SD3, qkv + 1024, 3 * DIM, SD3,
                             part, SEQ, SS, SEQ, SEQ, DIM, 1.0f, BATCH, 2, SKS_S);
        softmax_split_kernel<<<BATCH * SEQ, 256>>>(part, SKS_S, s, 1.0f / 32.0f);
        // a = attn @ V (split-K=2, BN=64 + reduce)
        gemm<MODE_PLAIN, 64>(s, SEQ, SS, vt, SEQ, SD, part, DIM, SD,
                             SEQ, DIM, SEQ, 1.0f, BATCH, 2, SKS_D);
        reduce_kernel<<<RED_GRID, 256>>>(part, SKS_D, nullptr, a);
        // h = a @ Wo^T + h (split-K=2, BN=64 + reduce w/ residual)
        gemm<MODE_PLAIN, 64>(a, DIM, 0, Wo, DIM, 0, part, DIM, 0,
                             MTOK, DIM, DIM, 1.0f, 1, 2, SKS_D);
        reduce_kernel<<<RED_GRID, 256>>>(part, SKS_D, h, h);
        // t = silu(h@Wg^T) * (h@Wu^T)
        gemm<MODE_SILU, 128>(h, DIM, 0, Wgu, DIM, 0, t, FFDIM, 0,
                             MTOK, 2 * FFDIM, DIM, 1.0f, 1);
        // h = t @ Wd^T + h (split-K=2, BN=64 + reduce w/ residual)
        gemm<MODE_PLAIN, 64>(t, FFDIM, 0, Wd, FFDIM, 0, part, DIM, 0,
                             MTOK, DIM, FFDIM, 1.0f, 1, 2, SKS_D);
        reduce_kernel<<<RED_GRID, 256>>>(part, SKS_D, h, h);
    }

    gemm<MODE_PLAIN, 128>(h, DIM, 0, w + 2 * LAYER_STRIDE, DIM, 0, out, VOC, 0,
                          MTOK, VOC, DIM, 1.0f, 1);
}